// round 11
// baseline (speedup 1.0000x reference)
#include <cuda_runtime.h>
#include <cstdint>
#include <cstddef>

// Problem dims
#define S_LEN 4096
#define HID   1024
#define EMB   1024
#define G4H   4096   // 4*HID
#define NBLK  128    // persistent recurrence blocks (1 per SM)
#define UPB   8      // hidden units per block (128*8 = 1024)

// ---------------- scratch (static device memory; no allocation) ----------------
__device__ __align__(16) float g_xgates[(size_t)S_LEN * G4H];   // 67 MB
__device__ __align__(16) float g_hs[(size_t)(S_LEN + 1) * HID]; // h history (head input)
// Sync slots: {f32 h (lo32), u32 step-tag (hi32)} packed u64, double-buffered by parity.
__device__ __align__(16) unsigned long long g_slot[2][HID];
__device__ int   g_cnt;                                          // completion hint counter
__device__ float g_v[HID];                                       // W_tag^T @ w_hyb
__device__ float g_bc;                                           // b_tag.w_hyb + b_hyb

// ---------------- helpers (morally-strong relaxed ops: coherent, per-address atomic) ----------------
__device__ __forceinline__ int ld_rlx32(const int* p) {
    int v;
    asm volatile("ld.global.relaxed.gpu.b32 %0, [%1];" : "=r"(v) : "l"(p) : "memory");
    return v;
}
__device__ __forceinline__ unsigned long long ld_rlx64(const unsigned long long* p) {
    unsigned long long v;
    asm volatile("ld.global.relaxed.gpu.b64 %0, [%1];" : "=l"(v) : "l"(p) : "memory");
    return v;
}
__device__ __forceinline__ void st_rlx64(unsigned long long* p, unsigned long long v) {
    asm volatile("st.global.relaxed.gpu.b64 [%0], %1;" :: "l"(p), "l"(v) : "memory");
}
__device__ __forceinline__ void red_add_relaxed(int* p, int v) {
    asm volatile("red.relaxed.gpu.global.add.s32 [%0], %1;" :: "l"(p), "r"(v) : "memory");
}
__device__ __forceinline__ void fma2(unsigned long long& d, unsigned long long a, unsigned long long b) {
    asm("fma.rn.f32x2 %0, %1, %2, %0;" : "+l"(d) : "l"(a), "l"(b));
}
__device__ __forceinline__ float2 unpack2(unsigned long long v) {
    float2 f;
    asm("mov.b64 {%0,%1}, %2;" : "=f"(f.x), "=f"(f.y) : "l"(v));
    return f;
}
__device__ __forceinline__ float sigm(float x) { return 1.f / (1.f + __expf(-x)); }
__device__ __forceinline__ float tanh_fast(float x) { return 2.f / (1.f + __expf(-2.f * x)) - 1.f; }

// ---------------- init: slots reset (both buffers), counter = 0, head bias constant ----------------
__global__ void init_kernel(const float* __restrict__ b_tag,
                            const float* __restrict__ w_hyb,
                            const float* __restrict__ b_hyb) {
    int tid = threadIdx.x;               // 1024 threads
    if (tid < HID) {
        g_slot[0][tid] = 0ull;                       // h(0)=0.0f, tag=0 (step 0 ready)
        g_slot[1][tid] = 0xFFFFFFFF00000000ull;      // invalid tag
    }
    if (tid == 0) g_cnt = 0;
    if (tid < 32) {
        float s = 0.f;
        for (int k = tid; k < HID; k += 32) s = fmaf(b_tag[k], w_hyb[k], s);
        #pragma unroll
        for (int o = 16; o; o >>= 1) s += __shfl_xor_sync(0xffffffffu, s, o);
        if (tid == 0) g_bc = s + b_hyb[0];
    }
}

// ---------------- head precompute: v[j] = sum_t w_hyb[t] * W_tag[t][j] ----------------
__global__ void vprec_kernel(const float* __restrict__ W_tag,
                             const float* __restrict__ w_hyb) {
    int j = threadIdx.x;  // 1024 threads
    float s = 0.f;
    #pragma unroll 8
    for (int t = 0; t < HID; t++)
        s = fmaf(__ldg(&w_hyb[t]), __ldg(&W_tag[(size_t)t * HID + j]), s);
    g_v[j] = s;
}

// ---------------- front GEMM: g_xgates[s][n] = emb[sentence[s]] . W_ih[n] + bias ----------------
#define GBM 128
#define GBN 128
#define GBK 8

__global__ void __launch_bounds__(256) gemm_xgates(
    const int*   __restrict__ sentence,
    const float* __restrict__ emb,
    const float* __restrict__ W_ih,
    const float* __restrict__ b_ih,
    const float* __restrict__ b_hh) {
    __shared__ int sids[GBM];
    __shared__ __align__(16) float As[2][GBK][GBM + 4];
    __shared__ __align__(16) float Bs[2][GBK][GBN + 4];

    int tid = threadIdx.x;
    int bm = blockIdx.y, bn = blockIdx.x;
    int tx = tid & 15, ty = tid >> 4;
    int lrow = tid >> 1;
    int lk   = (tid & 1) << 2;

    if (tid < GBM) sids[tid] = __ldg(&sentence[bm * GBM + tid]);
    __syncthreads();

    const float* aptr = emb + (size_t)sids[lrow] * EMB + lk;
    const float* bptr = W_ih + (size_t)(bn * GBN + lrow) * EMB + lk;

    {
        float4 av = *(const float4*)aptr;
        float4 bv = *(const float4*)bptr;
        As[0][lk + 0][lrow] = av.x; As[0][lk + 1][lrow] = av.y;
        As[0][lk + 2][lrow] = av.z; As[0][lk + 3][lrow] = av.w;
        Bs[0][lk + 0][lrow] = bv.x; Bs[0][lk + 1][lrow] = bv.y;
        Bs[0][lk + 2][lrow] = bv.z; Bs[0][lk + 3][lrow] = bv.w;
    }
    __syncthreads();

    float acc[8][8] = {};
    int cur = 0;
    for (int kt = GBK; kt <= EMB; kt += GBK) {
        bool more = (kt < EMB);
        float4 av, bv;
        if (more) {
            av = *(const float4*)(aptr + kt);
            bv = *(const float4*)(bptr + kt);
        }
        #pragma unroll
        for (int kk = 0; kk < GBK; kk++) {
            float4 a0 = *(const float4*)&As[cur][kk][ty << 3];
            float4 a1 = *(const float4*)&As[cur][kk][(ty << 3) + 4];
            float4 b0 = *(const float4*)&Bs[cur][kk][tx << 3];
            float4 b1 = *(const float4*)&Bs[cur][kk][(tx << 3) + 4];
            float am[8] = {a0.x, a0.y, a0.z, a0.w, a1.x, a1.y, a1.z, a1.w};
            float bb[8] = {b0.x, b0.y, b0.z, b0.w, b1.x, b1.y, b1.z, b1.w};
            #pragma unroll
            for (int i = 0; i < 8; i++)
                #pragma unroll
                for (int j = 0; j < 8; j++)
                    acc[i][j] = fmaf(am[i], bb[j], acc[i][j]);
        }
        if (more) {
            int nxt = cur ^ 1;
            As[nxt][lk + 0][lrow] = av.x; As[nxt][lk + 1][lrow] = av.y;
            As[nxt][lk + 2][lrow] = av.z; As[nxt][lk + 3][lrow] = av.w;
            Bs[nxt][lk + 0][lrow] = bv.x; Bs[nxt][lk + 1][lrow] = bv.y;
            Bs[nxt][lk + 2][lrow] = bv.z; Bs[nxt][lk + 3][lrow] = bv.w;
            __syncthreads();
            cur = nxt;
        }
    }

    int n0 = bn * GBN + (tx << 3);
    float4 bi0 = *(const float4*)&b_ih[n0];
    float4 bi1 = *(const float4*)&b_ih[n0 + 4];
    float4 bh0 = *(const float4*)&b_hh[n0];
    float4 bh1 = *(const float4*)&b_hh[n0 + 4];
    float4 bl0, bl1;
    bl0.x = bi0.x + bh0.x; bl0.y = bi0.y + bh0.y;
    bl0.z = bi0.z + bh0.z; bl0.w = bi0.w + bh0.w;
    bl1.x = bi1.x + bh1.x; bl1.y = bi1.y + bh1.y;
    bl1.z = bi1.z + bh1.z; bl1.w = bi1.w + bh1.w;
    #pragma unroll
    for (int i = 0; i < 8; i++) {
        int m = bm * GBM + (ty << 3) + i;
        float4 o0, o1;
        o0.x = acc[i][0] + bl0.x; o0.y = acc[i][1] + bl0.y;
        o0.z = acc[i][2] + bl0.z; o0.w = acc[i][3] + bl0.w;
        o1.x = acc[i][4] + bl1.x; o1.y = acc[i][5] + bl1.y;
        o1.z = acc[i][6] + bl1.z; o1.w = acc[i][7] + bl1.w;
        float* dst = &g_xgates[(size_t)m * G4H + n0];
        *(float4*)dst = o0;
        *(float4*)(dst + 4) = o1;
    }
}

// ---------------- persistent LSTM recurrence: tagged slots + pipelined hint poll ----------------
// 128 blocks x 1024 threads. Block b owns hidden units [8b, 8b+8).
// Publish: tail lanes st.relaxed.b64 {h, tag=t} FIRST (critical), then history store;
//          lane0 red.relaxed(g_cnt, 1) as a pacing HINT.
// Wait:    warp1 lane0 polls the hint with FOUR independent in-flight relaxed loads
//          (sample period ~RT/4 instead of RT -> detection lag ~1.1RT vs 1.5RT);
//          barrier; tid<256 read 4 slots each once, tag-verify, stage to smem.
__global__ void __launch_bounds__(1024, 1) lstm_rec(const float* __restrict__ W_hh) {
    __shared__ __align__(16) unsigned long long sh_h[HID / 2];  // h pairs
    __shared__ float part_s[8][4][4][4];

    int tid  = threadIdx.x;
    int lane = tid & 31, warp = tid >> 5;
    int group = warp >> 2, chunk = warp & 3;
    int b = blockIdx.x;
    int unit = b * UPB + group;

    // Packed register weights: w2[j][k] covers h pairs (chunk*128 + lane + 32k)
    unsigned long long w2[4][4];
    #pragma unroll
    for (int j = 0; j < 4; j++) {
        const float* wr = W_hh + (size_t)(j * HID + unit) * HID + (chunk << 8) + (lane << 1);
        #pragma unroll
        for (int k = 0; k < 4; k++)
            w2[j][k] = *(const unsigned long long*)(wr + 64 * k);
    }

    float c_reg = 0.f;
    float xg_cur = 0.f;
    if (warp == 0)
        xg_cur = __ldg(&g_xgates[(size_t)0 * G4H + (lane & 3) * HID + b * UPB + (lane >> 2)]);

    __syncthreads();

    int tgt = 0;  // = NBLK * (t-1)
    for (int t = 1; t <= S_LEN; t++, tgt += NBLK) {
        // Hint poll: warp1 lane0, 4 independent loads in flight (fast sampling)
        if (tid == 32) {
            const int* cp = &g_cnt;
            int a0 = ld_rlx32(cp);
            if (a0 < tgt) {
                int a1 = ld_rlx32(cp);
                int a2 = ld_rlx32(cp);
                int a3 = ld_rlx32(cp);
                for (;;) {
                    if (a0 >= tgt) break;
                    a0 = ld_rlx32(cp);
                    if (a1 >= tgt) break;
                    a1 = ld_rlx32(cp);
                    if (a2 >= tgt) break;
                    a2 = ld_rlx32(cp);
                    if (a3 >= tgt) break;
                    a3 = ld_rlx32(cp);
                }
            }
        }
        __syncthreads();  // A: hint observed -> slots are (almost surely) visible

        // Warp 0: prefetch next step's xg (DRAM latency hidden across the step)
        float xg_nxt = 0.f;
        if (warp == 0) {
            int tp = (t < S_LEN) ? t : 0;
            xg_nxt = __ldg(&g_xgates[(size_t)tp * G4H + (lane & 3) * HID + b * UPB + (lane >> 2)]);
        }

        // Stage: tid<256 read 4 slots each once; tags verify payload; retry stragglers
        if (tid < 256) {
            const unsigned long long* sp = &g_slot[(t - 1) & 1][tid << 2];
            const unsigned want = (unsigned)(t - 1);
            unsigned long long s0, s1, s2, s3;
            for (;;) {
                s0 = ld_rlx64(sp + 0);
                s1 = ld_rlx64(sp + 1);
                s2 = ld_rlx64(sp + 2);
                s3 = ld_rlx64(sp + 3);
                unsigned ok = ((unsigned)(s0 >> 32) == want) & ((unsigned)(s1 >> 32) == want)
                            & ((unsigned)(s2 >> 32) == want) & ((unsigned)(s3 >> 32) == want);
                if (ok) break;
            }
            unsigned long long p0 = (unsigned long long)(unsigned)s0 | (s1 << 32);
            unsigned long long p1 = (unsigned long long)(unsigned)s2 | (s3 << 32);
            sh_h[(tid << 1) + 0] = p0;
            sh_h[(tid << 1) + 1] = p1;
        }
        __syncthreads();  // B: staged h visible block-wide

        // Dots: thread's 4 h pairs at sh_h[chunk*128 + lane + 32k] (conflict-free LDS)
        const unsigned long long* hp = &sh_h[(chunk << 7) + lane];
        unsigned long long h0 = hp[0], h1 = hp[32], h2 = hp[64], h3 = hp[96];

        unsigned long long a2_0 = 0ull, a2_1 = 0ull, a2_2 = 0ull, a2_3 = 0ull;
        fma2(a2_0, w2[0][0], h0); fma2(a2_1, w2[1][0], h0);
        fma2(a2_2, w2[2][0], h0); fma2(a2_3, w2[3][0], h0);
        fma2(a2_0, w2[0][1], h1); fma2(a2_1, w2[1][1], h1);
        fma2(a2_2, w2[2][1], h1); fma2(a2_3, w2[3][1], h1);
        fma2(a2_0, w2[0][2], h2); fma2(a2_1, w2[1][2], h2);
        fma2(a2_2, w2[2][2], h2); fma2(a2_3, w2[3][2], h2);
        fma2(a2_0, w2[0][3], h3); fma2(a2_1, w2[1][3], h3);
        fma2(a2_2, w2[2][3], h3); fma2(a2_3, w2[3][3], h3);

        float2 f0 = unpack2(a2_0), f1 = unpack2(a2_1), f2 = unpack2(a2_2), f3 = unpack2(a2_3);
        float s0 = f0.x + f0.y, s1 = f1.x + f1.y, s2 = f2.x + f2.y, s3 = f3.x + f3.y;

        #pragma unroll
        for (int o = 16; o >= 4; o >>= 1) {
            s0 += __shfl_xor_sync(0xffffffffu, s0, o);
            s1 += __shfl_xor_sync(0xffffffffu, s1, o);
            s2 += __shfl_xor_sync(0xffffffffu, s2, o);
            s3 += __shfl_xor_sync(0xffffffffu, s3, o);
        }
        if (lane < 4) {
            part_s[group][0][chunk][lane] = s0;
            part_s[group][1][chunk][lane] = s1;
            part_s[group][2][chunk][lane] = s2;
            part_s[group][3][chunk][lane] = s3;
        }
        __syncthreads();  // C

        // Warp 0 tail: lane r = gate row (unit u=r>>2, gate j=r&3)
        if (warp == 0) {
            int u = lane >> 2, j = lane & 3;
            const float4* pp = (const float4*)&part_s[u][j][0][0];
            float4 p0 = pp[0], p1 = pp[1], p2 = pp[2], p3 = pp[3];
            float s = ((p0.x + p0.y) + (p0.z + p0.w)) + ((p1.x + p1.y) + (p1.z + p1.w))
                    + ((p2.x + p2.y) + (p2.z + p2.w)) + ((p3.x + p3.y) + (p3.z + p3.w))
                    + xg_cur;
            float act = (j == 2) ? tanh_fast(s) : sigm(s);
            float fv = __shfl_down_sync(0xffffffffu, act, 1);
            float gv = __shfl_down_sync(0xffffffffu, act, 2);
            float ov = __shfl_down_sync(0xffffffffu, act, 3);
            if (j == 0) {
                c_reg = fmaf(fv, c_reg, act * gv);          // act = i
                float h = ov * tanh_fast(c_reg);
                unsigned long long pkt =
                    ((unsigned long long)(unsigned)t << 32) | (unsigned long long)__float_as_uint(h);
                st_rlx64(&g_slot[t & 1][b * UPB + u], pkt); // CRITICAL: slot first
                g_hs[(size_t)t * HID + b * UPB + u] = h;    // history (head), off-path
            }
            __syncwarp();
            if (lane == 0) red_add_relaxed(&g_cnt, 1);      // hint only (tags carry truth)
            xg_cur = xg_nxt;
        }
    }
}

// ---------------- head: out[s] = sigmoid(hs(s+1) . v + bc) ----------------
__global__ void head_kernel(float* __restrict__ out) {
    int s = blockIdx.x;
    int tid = threadIdx.x;  // 128
    const float* hrow = g_hs + (size_t)(s + 1) * HID;
    float p = 0.f;
    #pragma unroll
    for (int k = 0; k < 8; k++)
        p = fmaf(hrow[tid + 128 * k], g_v[tid + 128 * k], p);
    #pragma unroll
    for (int o = 16; o; o >>= 1) p += __shfl_xor_sync(0xffffffffu, p, o);
    __shared__ float red[4];
    if ((tid & 31) == 0) red[tid >> 5] = p;
    __syncthreads();
    if (tid == 0) {
        float tot = red[0] + red[1] + red[2] + red[3] + g_bc;
        out[s] = sigm(tot);
    }
}

// ---------------- launch ----------------
extern "C" void kernel_launch(void* const* d_in, const int* in_sizes, int n_in,
                              void* d_out, int out_size) {
    const int*   sentence = (const int*)  d_in[0];
    const float* emb      = (const float*)d_in[1];
    const float* W_ih     = (const float*)d_in[2];
    const float* W_hh     = (const float*)d_in[3];
    const float* b_ih     = (const float*)d_in[4];
    const float* b_hh     = (const float*)d_in[5];
    const float* W_tag    = (const float*)d_in[6];
    const float* b_tag    = (const float*)d_in[7];
    const float* W_hyb    = (const float*)d_in[8];
    const float* b_hyb    = (const float*)d_in[9];
    float* out = (float*)d_out;

    init_kernel<<<1, 1024>>>(b_tag, W_hyb, b_hyb);
    vprec_kernel<<<1, 1024>>>(W_tag, W_hyb);
    dim3 g(G4H / GBN, S_LEN / GBM);
    gemm_xgates<<<g, 256>>>(sentence, emb, W_ih, b_ih, b_hh);
    lstm_rec<<<NBLK, 1024>>>(W_hh);
    head_kernel<<<S_LEN, 128>>>(out);
}

// round 12
// speedup vs baseline: 1.1616x; 1.1616x over previous
#include <cuda_runtime.h>
#include <cstdint>
#include <cstddef>

// Problem dims
#define S_LEN 4096
#define HID   1024
#define EMB   1024
#define G4H   4096   // 4*HID
#define NBLK  128    // persistent recurrence blocks (1 per SM)
#define UPB   8      // hidden units per block (128*8 = 1024)

// ---------------- scratch (static device memory; no allocation) ----------------
__device__ __align__(16) float g_xgates[(size_t)S_LEN * G4H];   // 67 MB
__device__ __align__(16) float g_hs[(size_t)(S_LEN + 1) * HID]; // h history (head input)
// Sync slots: 4B range-encoded h. v = h + (q ? +3 : -3), q = (t>>1)&1, buffer = t&1.
// |h|<1 strictly => v in (2,4) or (-4,-2); phase is carried inside the payload.
__device__ __align__(16) float g_slot[2][HID];
__device__ int   g_cnt;                                          // completion hint counter
__device__ float g_v[HID];                                       // W_tag^T @ w_hyb
__device__ float g_bc;                                           // b_tag.w_hyb + b_hyb

// ---------------- helpers (morally-strong relaxed ops: coherent, per-address atomic) ----------------
__device__ __forceinline__ int ld_rlx32(const int* p) {
    int v;
    asm volatile("ld.global.relaxed.gpu.b32 %0, [%1];" : "=r"(v) : "l"(p) : "memory");
    return v;
}
__device__ __forceinline__ unsigned long long ld_rlx64(const unsigned long long* p) {
    unsigned long long v;
    asm volatile("ld.global.relaxed.gpu.b64 %0, [%1];" : "=l"(v) : "l"(p) : "memory");
    return v;
}
__device__ __forceinline__ void st_rlx32f(float* p, float v) {
    asm volatile("st.global.relaxed.gpu.f32 [%0], %1;" :: "l"(p), "f"(v) : "memory");
}
__device__ __forceinline__ void red_add_relaxed(int* p, int v) {
    asm volatile("red.relaxed.gpu.global.add.s32 [%0], %1;" :: "l"(p), "r"(v) : "memory");
}
__device__ __forceinline__ void fma2(unsigned long long& d, unsigned long long a, unsigned long long b) {
    asm("fma.rn.f32x2 %0, %1, %2, %0;" : "+l"(d) : "l"(a), "l"(b));
}
__device__ __forceinline__ float2 unpack2(unsigned long long v) {
    float2 f;
    asm("mov.b64 {%0,%1}, %2;" : "=f"(f.x), "=f"(f.y) : "l"(v));
    return f;
}
__device__ __forceinline__ float sigm(float x) { return 1.f / (1.f + __expf(-x)); }
__device__ __forceinline__ float tanh_fast(float x) { return 2.f / (1.f + __expf(-2.f * x)) - 1.f; }

// ---------------- init: slots reset (both buffers), counter = 0, head bias constant ----------------
__global__ void init_kernel(const float* __restrict__ b_tag,
                            const float* __restrict__ w_hyb,
                            const float* __restrict__ b_hyb) {
    int tid = threadIdx.x;               // 1024 threads
    if (tid < HID) {
        g_slot[0][tid] = -3.f;           // step 0: h=0, q=0 -> v = 0 - 3
        g_slot[1][tid] = 0.f;            // invalid (in neither valid range)
    }
    if (tid == 0) g_cnt = 0;
    if (tid < 32) {
        float s = 0.f;
        for (int k = tid; k < HID; k += 32) s = fmaf(b_tag[k], w_hyb[k], s);
        #pragma unroll
        for (int o = 16; o; o >>= 1) s += __shfl_xor_sync(0xffffffffu, s, o);
        if (tid == 0) g_bc = s + b_hyb[0];
    }
}

// ---------------- head precompute: v[j] = sum_t w_hyb[t] * W_tag[t][j] ----------------
__global__ void vprec_kernel(const float* __restrict__ W_tag,
                             const float* __restrict__ w_hyb) {
    int j = threadIdx.x;  // 1024 threads
    float s = 0.f;
    #pragma unroll 8
    for (int t = 0; t < HID; t++)
        s = fmaf(__ldg(&w_hyb[t]), __ldg(&W_tag[(size_t)t * HID + j]), s);
    g_v[j] = s;
}

// ---------------- front GEMM: g_xgates[s][n] = emb[sentence[s]] . W_ih[n] + bias ----------------
#define GBM 128
#define GBN 128
#define GBK 8

__global__ void __launch_bounds__(256) gemm_xgates(
    const int*   __restrict__ sentence,
    const float* __restrict__ emb,
    const float* __restrict__ W_ih,
    const float* __restrict__ b_ih,
    const float* __restrict__ b_hh) {
    __shared__ int sids[GBM];
    __shared__ __align__(16) float As[2][GBK][GBM + 4];
    __shared__ __align__(16) float Bs[2][GBK][GBN + 4];

    int tid = threadIdx.x;
    int bm = blockIdx.y, bn = blockIdx.x;
    int tx = tid & 15, ty = tid >> 4;
    int lrow = tid >> 1;
    int lk   = (tid & 1) << 2;

    if (tid < GBM) sids[tid] = __ldg(&sentence[bm * GBM + tid]);
    __syncthreads();

    const float* aptr = emb + (size_t)sids[lrow] * EMB + lk;
    const float* bptr = W_ih + (size_t)(bn * GBN + lrow) * EMB + lk;

    {
        float4 av = *(const float4*)aptr;
        float4 bv = *(const float4*)bptr;
        As[0][lk + 0][lrow] = av.x; As[0][lk + 1][lrow] = av.y;
        As[0][lk + 2][lrow] = av.z; As[0][lk + 3][lrow] = av.w;
        Bs[0][lk + 0][lrow] = bv.x; Bs[0][lk + 1][lrow] = bv.y;
        Bs[0][lk + 2][lrow] = bv.z; Bs[0][lk + 3][lrow] = bv.w;
    }
    __syncthreads();

    float acc[8][8] = {};
    int cur = 0;
    for (int kt = GBK; kt <= EMB; kt += GBK) {
        bool more = (kt < EMB);
        float4 av, bv;
        if (more) {
            av = *(const float4*)(aptr + kt);
            bv = *(const float4*)(bptr + kt);
        }
        #pragma unroll
        for (int kk = 0; kk < GBK; kk++) {
            float4 a0 = *(const float4*)&As[cur][kk][ty << 3];
            float4 a1 = *(const float4*)&As[cur][kk][(ty << 3) + 4];
            float4 b0 = *(const float4*)&Bs[cur][kk][tx << 3];
            float4 b1 = *(const float4*)&Bs[cur][kk][(tx << 3) + 4];
            float am[8] = {a0.x, a0.y, a0.z, a0.w, a1.x, a1.y, a1.z, a1.w};
            float bb[8] = {b0.x, b0.y, b0.z, b0.w, b1.x, b1.y, b1.z, b1.w};
            #pragma unroll
            for (int i = 0; i < 8; i++)
                #pragma unroll
                for (int j = 0; j < 8; j++)
                    acc[i][j] = fmaf(am[i], bb[j], acc[i][j]);
        }
        if (more) {
            int nxt = cur ^ 1;
            As[nxt][lk + 0][lrow] = av.x; As[nxt][lk + 1][lrow] = av.y;
            As[nxt][lk + 2][lrow] = av.z; As[nxt][lk + 3][lrow] = av.w;
            Bs[nxt][lk + 0][lrow] = bv.x; Bs[nxt][lk + 1][lrow] = bv.y;
            Bs[nxt][lk + 2][lrow] = bv.z; Bs[nxt][lk + 3][lrow] = bv.w;
            __syncthreads();
            cur = nxt;
        }
    }

    int n0 = bn * GBN + (tx << 3);
    float4 bi0 = *(const float4*)&b_ih[n0];
    float4 bi1 = *(const float4*)&b_ih[n0 + 4];
    float4 bh0 = *(const float4*)&b_hh[n0];
    float4 bh1 = *(const float4*)&b_hh[n0 + 4];
    float4 bl0, bl1;
    bl0.x = bi0.x + bh0.x; bl0.y = bi0.y + bh0.y;
    bl0.z = bi0.z + bh0.z; bl0.w = bi0.w + bh0.w;
    bl1.x = bi1.x + bh1.x; bl1.y = bi1.y + bh1.y;
    bl1.z = bi1.z + bh1.z; bl1.w = bi1.w + bh1.w;
    #pragma unroll
    for (int i = 0; i < 8; i++) {
        int m = bm * GBM + (ty << 3) + i;
        float4 o0, o1;
        o0.x = acc[i][0] + bl0.x; o0.y = acc[i][1] + bl0.y;
        o0.z = acc[i][2] + bl0.z; o0.w = acc[i][3] + bl0.w;
        o1.x = acc[i][4] + bl1.x; o1.y = acc[i][5] + bl1.y;
        o1.z = acc[i][6] + bl1.z; o1.w = acc[i][7] + bl1.w;
        float* dst = &g_xgates[(size_t)m * G4H + n0];
        *(float4*)dst = o0;
        *(float4*)(dst + 4) = o1;
    }
}

// ---------------- persistent LSTM recurrence: 4B range-encoded slots + hint counter ----------------
// 128 blocks x 1024 threads. Block b owns hidden units [8b, 8b+8).
// Publish: warp0 (j==0) lanes st.relaxed.f32 (h + q?3:-3) to g_slot[t&1][unit]
//          (phase q=(t>>1)&1 is carried inside the value; worst-case stale data is
//           step t-3 which has the opposite phase -> always distinguishable);
//          then lane0 red.relaxed(g_cnt, 1) as a pacing HINT.
// Wait:    warp1 lane0 polls the hint (2-deep, proven); barrier; tid<256 read
//          2x u64 (4 slots) each, range-verify each 4B half, decode (exact
//          Sterbenz subtract), stage to smem; retry only rare stragglers.
__global__ void __launch_bounds__(1024, 1) lstm_rec(const float* __restrict__ W_hh) {
    __shared__ __align__(16) float sh_h[HID];
    __shared__ float part_s[8][4][4][4];

    int tid  = threadIdx.x;
    int lane = tid & 31, warp = tid >> 5;
    int group = warp >> 2, chunk = warp & 3;
    int b = blockIdx.x;
    int unit = b * UPB + group;

    // Packed register weights: w2[j][k] covers h pairs (chunk*128 + lane + 32k)
    unsigned long long w2[4][4];
    #pragma unroll
    for (int j = 0; j < 4; j++) {
        const float* wr = W_hh + (size_t)(j * HID + unit) * HID + (chunk << 8) + (lane << 1);
        #pragma unroll
        for (int k = 0; k < 4; k++)
            w2[j][k] = *(const unsigned long long*)(wr + 64 * k);
    }

    float c_reg = 0.f;
    float xg_cur = 0.f;
    if (warp == 0)
        xg_cur = __ldg(&g_xgates[(size_t)0 * G4H + (lane & 3) * HID + b * UPB + (lane >> 2)]);

    __syncthreads();

    int tgt = 0;  // = NBLK * (t-1)
    for (int t = 1; t <= S_LEN; t++, tgt += NBLK) {
        // Hint poll: warp1 lane0, 2-deep pipelined relaxed loads (R10-proven)
        if (tid == 32) {
            for (;;) {
                int a = ld_rlx32(&g_cnt);
                if (a >= tgt) break;
                int c = ld_rlx32(&g_cnt);
                if (c >= tgt) break;
            }
        }
        __syncthreads();  // A: hint observed -> slots are (almost surely) visible

        // Warp 0: prefetch next step's xg (DRAM latency hidden across the step)
        float xg_nxt = 0.f;
        if (warp == 0) {
            int tp = (t < S_LEN) ? t : 0;
            xg_nxt = __ldg(&g_xgates[(size_t)tp * G4H + (lane & 3) * HID + b * UPB + (lane >> 2)]);
        }

        // Stage: tid<256 read 4 slots (2 x u64) each; range-verify 4B halves; decode
        if (tid < 256) {
            const unsigned long long* sp =
                (const unsigned long long*)&g_slot[(t - 1) & 1][tid << 2];
            const float off = (((t - 1) >> 1) & 1) ? 3.f : -3.f;   // writer's phase offset
            const float sgn = (((t - 1) >> 1) & 1) ? 1.f : -1.f;   // valid iff v*sgn > 1.5
            float4 hv;
            for (;;) {
                unsigned long long s0 = ld_rlx64(sp + 0);
                unsigned long long s1 = ld_rlx64(sp + 1);
                float2 a = unpack2(s0), c = unpack2(s1);
                bool ok = (a.x * sgn > 1.5f) & (a.y * sgn > 1.5f)
                        & (c.x * sgn > 1.5f) & (c.y * sgn > 1.5f);
                if (ok) {
                    hv.x = a.x - off; hv.y = a.y - off;   // exact (Sterbenz)
                    hv.z = c.x - off; hv.w = c.y - off;
                    break;
                }
            }
            *(float4*)&sh_h[tid << 2] = hv;
        }
        __syncthreads();  // B: staged h visible block-wide

        // Dots: thread's 4 h pairs at pair index chunk*128 + lane + 32k (conflict-free LDS)
        const unsigned long long* hp = (const unsigned long long*)sh_h + (chunk << 7) + lane;
        unsigned long long h0 = hp[0], h1 = hp[32], h2 = hp[64], h3 = hp[96];

        unsigned long long a2_0 = 0ull, a2_1 = 0ull, a2_2 = 0ull, a2_3 = 0ull;
        fma2(a2_0, w2[0][0], h0); fma2(a2_1, w2[1][0], h0);
        fma2(a2_2, w2[2][0], h0); fma2(a2_3, w2[3][0], h0);
        fma2(a2_0, w2[0][1], h1); fma2(a2_1, w2[1][1], h1);
        fma2(a2_2, w2[2][1], h1); fma2(a2_3, w2[3][1], h1);
        fma2(a2_0, w2[0][2], h2); fma2(a2_1, w2[1][2], h2);
        fma2(a2_2, w2[2][2], h2); fma2(a2_3, w2[3][2], h2);
        fma2(a2_0, w2[0][3], h3); fma2(a2_1, w2[1][3], h3);
        fma2(a2_2, w2[2][3], h3); fma2(a2_3, w2[3][3], h3);

        float2 f0 = unpack2(a2_0), f1 = unpack2(a2_1), f2 = unpack2(a2_2), f3 = unpack2(a2_3);
        float s0 = f0.x + f0.y, s1 = f1.x + f1.y, s2 = f2.x + f2.y, s3 = f3.x + f3.y;

        #pragma unroll
        for (int o = 16; o >= 4; o >>= 1) {
            s0 += __shfl_xor_sync(0xffffffffu, s0, o);
            s1 += __shfl_xor_sync(0xffffffffu, s1, o);
            s2 += __shfl_xor_sync(0xffffffffu, s2, o);
            s3 += __shfl_xor_sync(0xffffffffu, s3, o);
        }
        if (lane < 4) {
            part_s[group][0][chunk][lane] = s0;
            part_s[group][1][chunk][lane] = s1;
            part_s[group][2][chunk][lane] = s2;
            part_s[group][3][chunk][lane] = s3;
        }
        __syncthreads();  // C

        // Warp 0 tail: lane r = gate row (unit u=r>>2, gate j=r&3)
        if (warp == 0) {
            int u = lane >> 2, j = lane & 3;
            const float4* pp = (const float4*)&part_s[u][j][0][0];
            float4 p0 = pp[0], p1 = pp[1], p2 = pp[2], p3 = pp[3];
            float s = ((p0.x + p0.y) + (p0.z + p0.w)) + ((p1.x + p1.y) + (p1.z + p1.w))
                    + ((p2.x + p2.y) + (p2.z + p2.w)) + ((p3.x + p3.y) + (p3.z + p3.w))
                    + xg_cur;
            float act = (j == 2) ? tanh_fast(s) : sigm(s);
            float fv = __shfl_down_sync(0xffffffffu, act, 1);
            float gv = __shfl_down_sync(0xffffffffu, act, 2);
            float ov = __shfl_down_sync(0xffffffffu, act, 3);
            if (j == 0) {
                c_reg = fmaf(fv, c_reg, act * gv);          // act = i
                float h = ov * tanh_fast(c_reg);
                g_hs[(size_t)t * HID + b * UPB + u] = h;    // history (head), off-path
                float woff = ((t >> 1) & 1) ? 3.f : -3.f;   // this step's phase offset
                st_rlx32f(&g_slot[t & 1][b * UPB + u], h + woff);
            }
            __syncwarp();
            if (lane == 0) red_add_relaxed(&g_cnt, 1);      // hint only (ranges carry truth)
            xg_cur = xg_nxt;
        }
    }
}

// ---------------- head: out[s] = sigmoid(hs(s+1) . v + bc) ----------------
__global__ void head_kernel(float* __restrict__ out) {
    int s = blockIdx.x;
    int tid = threadIdx.x;  // 128
    const float* hrow = g_hs + (size_t)(s + 1) * HID;
    float p = 0.f;
    #pragma unroll
    for (int k = 0; k < 8; k++)
        p = fmaf(hrow[tid + 128 * k], g_v[tid + 128 * k], p);
    #pragma unroll
    for (int o = 16; o; o >>= 1) p += __shfl_xor_sync(0xffffffffu, p, o);
    __shared__ float red[4];
    if ((tid & 31) == 0) red[tid >> 5] = p;
    __syncthreads();
    if (tid == 0) {
        float tot = red[0] + red[1] + red[2] + red[3] + g_bc;
        out[s] = sigm(tot);
    }
}

// ---------------- launch ----------------
extern "C" void kernel_launch(void* const* d_in, const int* in_sizes, int n_in,
                              void* d_out, int out_size) {
    const int*   sentence = (const int*)  d_in[0];
    const float* emb      = (const float*)d_in[1];
    const float* W_ih     = (const float*)d_in[2];
    const float* W_hh     = (const float*)d_in[3];
    const float* b_ih     = (const float*)d_in[4];
    const float* b_hh     = (const float*)d_in[5];
    const float* W_tag    = (const float*)d_in[6];
    const float* b_tag    = (const float*)d_in[7];
    const float* W_hyb    = (const float*)d_in[8];
    const float* b_hyb    = (const float*)d_in[9];
    float* out = (float*)d_out;

    init_kernel<<<1, 1024>>>(b_tag, W_hyb, b_hyb);
    vprec_kernel<<<1, 1024>>>(W_tag, W_hyb);
    dim3 g(G4H / GBN, S_LEN / GBM);
    gemm_xgates<<<g, 256>>>(sentence, emb, W_ih, b_ih, b_hh);
    lstm_rec<<<NBLK, 1024>>>(W_hh);
    head_kernel<<<S_LEN, 128>>>(out);
}

// round 13
// speedup vs baseline: 1.1805x; 1.0163x over previous
#include <cuda_runtime.h>
#include <cstdint>
#include <cstddef>

// Problem dims
#define S_LEN 4096
#define HID   1024
#define EMB   1024
#define G4H   4096   // 4*HID
#define NBLK  128    // persistent recurrence blocks (1 per SM)
#define UPB   8      // hidden units per block (128*8 = 1024)
#define EARLY 24     // hint-poll early-release margin (stagers' retry absorbs stragglers)

// ---------------- scratch (static device memory; no allocation) ----------------
__device__ __align__(16) float g_xgates[(size_t)S_LEN * G4H];   // 67 MB
__device__ __align__(16) float g_hs[(size_t)(S_LEN + 1) * HID]; // h history (head input)
// Sync slots: 4B range-encoded h. v = h + (q ? +3 : -3), q = (t>>1)&1, buffer = t&1.
// |h|<1 strictly => v in (2,4) or (-4,-2); phase is carried inside the payload.
__device__ __align__(16) float g_slot[2][HID];
__device__ int   g_cnt;                                          // completion hint counter
__device__ float g_v[HID];                                       // W_tag^T @ w_hyb
__device__ float g_bc;                                           // b_tag.w_hyb + b_hyb

// ---------------- helpers (morally-strong relaxed ops: coherent, per-address atomic) ----------------
__device__ __forceinline__ int ld_rlx32(const int* p) {
    int v;
    asm volatile("ld.global.relaxed.gpu.b32 %0, [%1];" : "=r"(v) : "l"(p) : "memory");
    return v;
}
__device__ __forceinline__ unsigned long long ld_rlx64(const unsigned long long* p) {
    unsigned long long v;
    asm volatile("ld.global.relaxed.gpu.b64 %0, [%1];" : "=l"(v) : "l"(p) : "memory");
    return v;
}
__device__ __forceinline__ void st_rlx32f(float* p, float v) {
    asm volatile("st.global.relaxed.gpu.f32 [%0], %1;" :: "l"(p), "f"(v) : "memory");
}
__device__ __forceinline__ void red_add_relaxed(int* p, int v) {
    asm volatile("red.relaxed.gpu.global.add.s32 [%0], %1;" :: "l"(p), "r"(v) : "memory");
}
__device__ __forceinline__ void fma2(unsigned long long& d, unsigned long long a, unsigned long long b) {
    asm("fma.rn.f32x2 %0, %1, %2, %0;" : "+l"(d) : "l"(a), "l"(b));
}
__device__ __forceinline__ float2 unpack2(unsigned long long v) {
    float2 f;
    asm("mov.b64 {%0,%1}, %2;" : "=f"(f.x), "=f"(f.y) : "l"(v));
    return f;
}
__device__ __forceinline__ float sigm(float x) { return 1.f / (1.f + __expf(-x)); }
__device__ __forceinline__ float tanh_fast(float x) { return 2.f / (1.f + __expf(-2.f * x)) - 1.f; }

// ---------------- init: slots reset (both buffers), counter = 0, head bias constant ----------------
__global__ void init_kernel(const float* __restrict__ b_tag,
                            const float* __restrict__ w_hyb,
                            const float* __restrict__ b_hyb) {
    int tid = threadIdx.x;               // 1024 threads
    if (tid < HID) {
        g_slot[0][tid] = -3.f;           // step 0: h=0, q=0 -> v = 0 - 3
        g_slot[1][tid] = 0.f;            // invalid (in neither valid range)
    }
    if (tid == 0) g_cnt = 0;
    if (tid < 32) {
        float s = 0.f;
        for (int k = tid; k < HID; k += 32) s = fmaf(b_tag[k], w_hyb[k], s);
        #pragma unroll
        for (int o = 16; o; o >>= 1) s += __shfl_xor_sync(0xffffffffu, s, o);
        if (tid == 0) g_bc = s + b_hyb[0];
    }
}

// ---------------- head precompute: v[j] = sum_t w_hyb[t] * W_tag[t][j] ----------------
__global__ void vprec_kernel(const float* __restrict__ W_tag,
                             const float* __restrict__ w_hyb) {
    int j = threadIdx.x;  // 1024 threads
    float s = 0.f;
    #pragma unroll 8
    for (int t = 0; t < HID; t++)
        s = fmaf(__ldg(&w_hyb[t]), __ldg(&W_tag[(size_t)t * HID + j]), s);
    g_v[j] = s;
}

// ---------------- front GEMM: g_xgates[s][n] = emb[sentence[s]] . W_ih[n] + bias ----------------
#define GBM 128
#define GBN 128
#define GBK 8

__global__ void __launch_bounds__(256) gemm_xgates(
    const int*   __restrict__ sentence,
    const float* __restrict__ emb,
    const float* __restrict__ W_ih,
    const float* __restrict__ b_ih,
    const float* __restrict__ b_hh) {
    __shared__ int sids[GBM];
    __shared__ __align__(16) float As[2][GBK][GBM + 4];
    __shared__ __align__(16) float Bs[2][GBK][GBN + 4];

    int tid = threadIdx.x;
    int bm = blockIdx.y, bn = blockIdx.x;
    int tx = tid & 15, ty = tid >> 4;
    int lrow = tid >> 1;
    int lk   = (tid & 1) << 2;

    if (tid < GBM) sids[tid] = __ldg(&sentence[bm * GBM + tid]);
    __syncthreads();

    const float* aptr = emb + (size_t)sids[lrow] * EMB + lk;
    const float* bptr = W_ih + (size_t)(bn * GBN + lrow) * EMB + lk;

    {
        float4 av = *(const float4*)aptr;
        float4 bv = *(const float4*)bptr;
        As[0][lk + 0][lrow] = av.x; As[0][lk + 1][lrow] = av.y;
        As[0][lk + 2][lrow] = av.z; As[0][lk + 3][lrow] = av.w;
        Bs[0][lk + 0][lrow] = bv.x; Bs[0][lk + 1][lrow] = bv.y;
        Bs[0][lk + 2][lrow] = bv.z; Bs[0][lk + 3][lrow] = bv.w;
    }
    __syncthreads();

    float acc[8][8] = {};
    int cur = 0;
    for (int kt = GBK; kt <= EMB; kt += GBK) {
        bool more = (kt < EMB);
        float4 av, bv;
        if (more) {
            av = *(const float4*)(aptr + kt);
            bv = *(const float4*)(bptr + kt);
        }
        #pragma unroll
        for (int kk = 0; kk < GBK; kk++) {
            float4 a0 = *(const float4*)&As[cur][kk][ty << 3];
            float4 a1 = *(const float4*)&As[cur][kk][(ty << 3) + 4];
            float4 b0 = *(const float4*)&Bs[cur][kk][tx << 3];
            float4 b1 = *(const float4*)&Bs[cur][kk][(tx << 3) + 4];
            float am[8] = {a0.x, a0.y, a0.z, a0.w, a1.x, a1.y, a1.z, a1.w};
            float bb[8] = {b0.x, b0.y, b0.z, b0.w, b1.x, b1.y, b1.z, b1.w};
            #pragma unroll
            for (int i = 0; i < 8; i++)
                #pragma unroll
                for (int j = 0; j < 8; j++)
                    acc[i][j] = fmaf(am[i], bb[j], acc[i][j]);
        }
        if (more) {
            int nxt = cur ^ 1;
            As[nxt][lk + 0][lrow] = av.x; As[nxt][lk + 1][lrow] = av.y;
            As[nxt][lk + 2][lrow] = av.z; As[nxt][lk + 3][lrow] = av.w;
            Bs[nxt][lk + 0][lrow] = bv.x; Bs[nxt][lk + 1][lrow] = bv.y;
            Bs[nxt][lk + 2][lrow] = bv.z; Bs[nxt][lk + 3][lrow] = bv.w;
            __syncthreads();
            cur = nxt;
        }
    }

    int n0 = bn * GBN + (tx << 3);
    float4 bi0 = *(const float4*)&b_ih[n0];
    float4 bi1 = *(const float4*)&b_ih[n0 + 4];
    float4 bh0 = *(const float4*)&b_hh[n0];
    float4 bh1 = *(const float4*)&b_hh[n0 + 4];
    float4 bl0, bl1;
    bl0.x = bi0.x + bh0.x; bl0.y = bi0.y + bh0.y;
    bl0.z = bi0.z + bh0.z; bl0.w = bi0.w + bh0.w;
    bl1.x = bi1.x + bh1.x; bl1.y = bi1.y + bh1.y;
    bl1.z = bi1.z + bh1.z; bl1.w = bi1.w + bh1.w;
    #pragma unroll
    for (int i = 0; i < 8; i++) {
        int m = bm * GBM + (ty << 3) + i;
        float4 o0, o1;
        o0.x = acc[i][0] + bl0.x; o0.y = acc[i][1] + bl0.y;
        o0.z = acc[i][2] + bl0.z; o0.w = acc[i][3] + bl0.w;
        o1.x = acc[i][4] + bl1.x; o1.y = acc[i][5] + bl1.y;
        o1.z = acc[i][6] + bl1.z; o1.w = acc[i][7] + bl1.w;
        float* dst = &g_xgates[(size_t)m * G4H + n0];
        *(float4*)dst = o0;
        *(float4*)(dst + 4) = o1;
    }
}

// ---------------- persistent LSTM recurrence: 4B slots + EARLY-release hint ----------------
// 128 blocks x 1024 threads. Block b owns hidden units [8b, 8b+8).
// Publish: warp0 (j==0) lanes st.relaxed.f32 (h + q?3:-3) to g_slot[t&1][unit];
//          lane0 red.relaxed(g_cnt, 1) as a pacing HINT.
// Wait:    warp1 lane0 polls cnt >= 128*(t-1) - EARLY (early release: ~104/128 done);
//          barrier; tid<256 stage 4 slots each with range-verified retry (the retry
//          absorbs the <=EARLY stragglers; ranges carry the actual correctness).
// Progress: a block can only PUBLISH step t after staging all of t-1, so block
// spread stays <= 1 step and every poll target is eventually reached.
__global__ void __launch_bounds__(1024, 1) lstm_rec(const float* __restrict__ W_hh) {
    __shared__ __align__(16) float sh_h[HID];
    __shared__ float part_s[8][4][4][4];

    int tid  = threadIdx.x;
    int lane = tid & 31, warp = tid >> 5;
    int group = warp >> 2, chunk = warp & 3;
    int b = blockIdx.x;
    int unit = b * UPB + group;

    // Packed register weights: w2[j][k] covers h pairs (chunk*128 + lane + 32k)
    unsigned long long w2[4][4];
    #pragma unroll
    for (int j = 0; j < 4; j++) {
        const float* wr = W_hh + (size_t)(j * HID + unit) * HID + (chunk << 8) + (lane << 1);
        #pragma unroll
        for (int k = 0; k < 4; k++)
            w2[j][k] = *(const unsigned long long*)(wr + 64 * k);
    }

    float c_reg = 0.f;
    float xg_cur = 0.f;
    if (warp == 0)
        xg_cur = __ldg(&g_xgates[(size_t)0 * G4H + (lane & 3) * HID + b * UPB + (lane >> 2)]);

    __syncthreads();

    int tgt = -EARLY;  // = NBLK * (t-1) - EARLY
    for (int t = 1; t <= S_LEN; t++, tgt += NBLK) {
        // Hint poll: warp1 lane0, 2-deep pipelined relaxed loads, EARLY-released
        if (tid == 32) {
            for (;;) {
                int a = ld_rlx32(&g_cnt);
                if (a >= tgt) break;
                int c = ld_rlx32(&g_cnt);
                if (c >= tgt) break;
            }
        }
        __syncthreads();  // A: most publishes observed; stragglers handled below

        // Warp 0: prefetch next step's xg (DRAM latency hidden across the step)
        float xg_nxt = 0.f;
        if (warp == 0) {
            int tp = (t < S_LEN) ? t : 0;
            xg_nxt = __ldg(&g_xgates[(size_t)tp * G4H + (lane & 3) * HID + b * UPB + (lane >> 2)]);
        }

        // Stage: tid<256 read 4 slots (2 x u64) each; range-verify 4B halves; decode
        if (tid < 256) {
            const unsigned long long* sp =
                (const unsigned long long*)&g_slot[(t - 1) & 1][tid << 2];
            const float off = (((t - 1) >> 1) & 1) ? 3.f : -3.f;   // writer's phase offset
            const float sgn = (((t - 1) >> 1) & 1) ? 1.f : -1.f;   // valid iff v*sgn > 1.5
            float4 hv;
            for (;;) {
                unsigned long long s0 = ld_rlx64(sp + 0);
                unsigned long long s1 = ld_rlx64(sp + 1);
                float2 a = unpack2(s0), c = unpack2(s1);
                bool ok = (a.x * sgn > 1.5f) & (a.y * sgn > 1.5f)
                        & (c.x * sgn > 1.5f) & (c.y * sgn > 1.5f);
                if (ok) {
                    hv.x = a.x - off; hv.y = a.y - off;   // exact (Sterbenz)
                    hv.z = c.x - off; hv.w = c.y - off;
                    break;
                }
            }
            *(float4*)&sh_h[tid << 2] = hv;
        }
        __syncthreads();  // B: staged h visible block-wide

        // Dots: thread's 4 h pairs at pair index chunk*128 + lane + 32k (conflict-free LDS)
        const unsigned long long* hp = (const unsigned long long*)sh_h + (chunk << 7) + lane;
        unsigned long long h0 = hp[0], h1 = hp[32], h2 = hp[64], h3 = hp[96];

        unsigned long long a2_0 = 0ull, a2_1 = 0ull, a2_2 = 0ull, a2_3 = 0ull;
        fma2(a2_0, w2[0][0], h0); fma2(a2_1, w2[1][0], h0);
        fma2(a2_2, w2[2][0], h0); fma2(a2_3, w2[3][0], h0);
        fma2(a2_0, w2[0][1], h1); fma2(a2_1, w2[1][1], h1);
        fma2(a2_2, w2[2][1], h1); fma2(a2_3, w2[3][1], h1);
        fma2(a2_0, w2[0][2], h2); fma2(a2_1, w2[1][2], h2);
        fma2(a2_2, w2[2][2], h2); fma2(a2_3, w2[3][2], h2);
        fma2(a2_0, w2[0][3], h3); fma2(a2_1, w2[1][3], h3);
        fma2(a2_2, w2[2][3], h3); fma2(a2_3, w2[3][3], h3);

        float2 f0 = unpack2(a2_0), f1 = unpack2(a2_1), f2 = unpack2(a2_2), f3 = unpack2(a2_3);
        float s0 = f0.x + f0.y, s1 = f1.x + f1.y, s2 = f2.x + f2.y, s3 = f3.x + f3.y;

        #pragma unroll
        for (int o = 16; o >= 4; o >>= 1) {
            s0 += __shfl_xor_sync(0xffffffffu, s0, o);
            s1 += __shfl_xor_sync(0xffffffffu, s1, o);
            s2 += __shfl_xor_sync(0xffffffffu, s2, o);
            s3 += __shfl_xor_sync(0xffffffffu, s3, o);
        }
        if (lane < 4) {
            part_s[group][0][chunk][lane] = s0;
            part_s[group][1][chunk][lane] = s1;
            part_s[group][2][chunk][lane] = s2;
            part_s[group][3][chunk][lane] = s3;
        }
        __syncthreads();  // C

        // Warp 0 tail: lane r = gate row (unit u=r>>2, gate j=r&3)
        if (warp == 0) {
            int u = lane >> 2, j = lane & 3;
            const float4* pp = (const float4*)&part_s[u][j][0][0];
            float4 p0 = pp[0], p1 = pp[1], p2 = pp[2], p3 = pp[3];
            float s = ((p0.x + p0.y) + (p0.z + p0.w)) + ((p1.x + p1.y) + (p1.z + p1.w))
                    + ((p2.x + p2.y) + (p2.z + p2.w)) + ((p3.x + p3.y) + (p3.z + p3.w))
                    + xg_cur;
            float act = (j == 2) ? tanh_fast(s) : sigm(s);
            float fv = __shfl_down_sync(0xffffffffu, act, 1);
            float gv = __shfl_down_sync(0xffffffffu, act, 2);
            float ov = __shfl_down_sync(0xffffffffu, act, 3);
            if (j == 0) {
                c_reg = fmaf(fv, c_reg, act * gv);          // act = i
                float h = ov * tanh_fast(c_reg);
                g_hs[(size_t)t * HID + b * UPB + u] = h;    // history (head), off-path
                float woff = ((t >> 1) & 1) ? 3.f : -3.f;   // this step's phase offset
                st_rlx32f(&g_slot[t & 1][b * UPB + u], h + woff);
            }
            __syncwarp();
            if (lane == 0) red_add_relaxed(&g_cnt, 1);      // hint only (ranges carry truth)
            xg_cur = xg_nxt;
        }
    }
}

// ---------------- head: out[s] = sigmoid(hs(s+1) . v + bc) ----------------
__global__ void head_kernel(float* __restrict__ out) {
    int s = blockIdx.x;
    int tid = threadIdx.x;  // 128
    const float* hrow = g_hs + (size_t)(s + 1) * HID;
    float p = 0.f;
    #pragma unroll
    for (int k = 0; k < 8; k++)
        p = fmaf(hrow[tid + 128 * k], g_v[tid + 128 * k], p);
    #pragma unroll
    for (int o = 16; o; o >>= 1) p += __shfl_xor_sync(0xffffffffu, p, o);
    __shared__ float red[4];
    if ((tid & 31) == 0) red[tid >> 5] = p;
    __syncthreads();
    if (tid == 0) {
        float tot = red[0] + red[1] + red[2] + red[3] + g_bc;
        out[s] = sigm(tot);
    }
}

// ---------------- launch ----------------
extern "C" void kernel_launch(void* const* d_in, const int* in_sizes, int n_in,
                              void* d_out, int out_size) {
    const int*   sentence = (const int*)  d_in[0];
    const float* emb      = (const float*)d_in[1];
    const float* W_ih     = (const float*)d_in[2];
    const float* W_hh     = (const float*)d_in[3];
    const float* b_ih     = (const float*)d_in[4];
    const float* b_hh     = (const float*)d_in[5];
    const float* W_tag    = (const float*)d_in[6];
    const float* b_tag    = (const float*)d_in[7];
    const float* W_hyb    = (const float*)d_in[8];
    const float* b_hyb    = (const float*)d_in[9];
    float* out = (float*)d_out;

    init_kernel<<<1, 1024>>>(b_tag, W_hyb, b_hyb);
    vprec_kernel<<<1, 1024>>>(W_tag, W_hyb);
    dim3 g(G4H / GBN, S_LEN / GBM);
    gemm_xgates<<<g, 256>>>(sentence, emb, W_ih, b_ih, b_hh);
    lstm_rec<<<NBLK, 1024>>>(W_hh);
    head_kernel<<<S_LEN, 128>>>(out);
}

// round 14
// speedup vs baseline: 1.2164x; 1.0305x over previous
#include <cuda_runtime.h>
#include <cstdint>
#include <cstddef>

// Problem dims
#define S_LEN 4096
#define HID   1024
#define EMB   1024
#define G4H   4096   // 4*HID
#define NBLK  128    // persistent recurrence blocks (1 per SM)
#define UPB   8      // hidden units per block (128*8 = 1024)
#define EARLY 48     // hint-poll early-release margin (stagers' retry absorbs stragglers)

// ---------------- scratch (static device memory; no allocation) ----------------
__device__ __align__(16) float g_xgates[(size_t)S_LEN * G4H];   // 67 MB
__device__ __align__(16) float g_hs[(size_t)(S_LEN + 1) * HID]; // h history (head input)
// Sync slots: 4B range-encoded h. v = h + (q ? +3 : -3), q = (t>>1)&1, buffer = t&1.
// |h|<1 strictly => v in (2,4) or (-4,-2); phase is carried inside the payload.
__device__ __align__(16) float g_slot[2][HID];
__device__ int   g_cnt;                                          // completion hint counter
__device__ float g_v[HID];                                       // W_tag^T @ w_hyb
__device__ float g_bc;                                           // b_tag.w_hyb + b_hyb

// ---------------- helpers (morally-strong relaxed ops: coherent, per-address atomic) ----------------
__device__ __forceinline__ int ld_rlx32(const int* p) {
    int v;
    asm volatile("ld.global.relaxed.gpu.b32 %0, [%1];" : "=r"(v) : "l"(p) : "memory");
    return v;
}
__device__ __forceinline__ unsigned long long ld_rlx64(const unsigned long long* p) {
    unsigned long long v;
    asm volatile("ld.global.relaxed.gpu.b64 %0, [%1];" : "=l"(v) : "l"(p) : "memory");
    return v;
}
__device__ __forceinline__ void st_rlx32f(float* p, float v) {
    asm volatile("st.global.relaxed.gpu.f32 [%0], %1;" :: "l"(p), "f"(v) : "memory");
}
__device__ __forceinline__ void red_add_relaxed(int* p, int v) {
    asm volatile("red.relaxed.gpu.global.add.s32 [%0], %1;" :: "l"(p), "r"(v) : "memory");
}
__device__ __forceinline__ void fma2(unsigned long long& d, unsigned long long a, unsigned long long b) {
    asm("fma.rn.f32x2 %0, %1, %2, %0;" : "+l"(d) : "l"(a), "l"(b));
}
__device__ __forceinline__ float2 unpack2(unsigned long long v) {
    float2 f;
    asm("mov.b64 {%0,%1}, %2;" : "=f"(f.x), "=f"(f.y) : "l"(v));
    return f;
}
__device__ __forceinline__ float sigm(float x) { return 1.f / (1.f + __expf(-x)); }
__device__ __forceinline__ float tanh_fast(float x) { return 2.f / (1.f + __expf(-2.f * x)) - 1.f; }

// ---------------- init: slots reset (both buffers), counter = 0, head bias constant ----------------
__global__ void init_kernel(const float* __restrict__ b_tag,
                            const float* __restrict__ w_hyb,
                            const float* __restrict__ b_hyb) {
    int tid = threadIdx.x;               // 1024 threads
    if (tid < HID) {
        g_slot[0][tid] = -3.f;           // step 0: h=0, q=0 -> v = 0 - 3
        g_slot[1][tid] = 0.f;            // invalid (in neither valid range)
    }
    if (tid == 0) g_cnt = 0;
    if (tid < 32) {
        float s = 0.f;
        for (int k = tid; k < HID; k += 32) s = fmaf(b_tag[k], w_hyb[k], s);
        #pragma unroll
        for (int o = 16; o; o >>= 1) s += __shfl_xor_sync(0xffffffffu, s, o);
        if (tid == 0) g_bc = s + b_hyb[0];
    }
}

// ---------------- head precompute: v[j] = sum_t w_hyb[t] * W_tag[t][j] ----------------
__global__ void vprec_kernel(const float* __restrict__ W_tag,
                             const float* __restrict__ w_hyb) {
    int j = threadIdx.x;  // 1024 threads
    float s = 0.f;
    #pragma unroll 8
    for (int t = 0; t < HID; t++)
        s = fmaf(__ldg(&w_hyb[t]), __ldg(&W_tag[(size_t)t * HID + j]), s);
    g_v[j] = s;
}

// ---------------- front GEMM: g_xgates[s][n] = emb[sentence[s]] . W_ih[n] + bias ----------------
#define GBM 128
#define GBN 128
#define GBK 8

__global__ void __launch_bounds__(256) gemm_xgates(
    const int*   __restrict__ sentence,
    const float* __restrict__ emb,
    const float* __restrict__ W_ih,
    const float* __restrict__ b_ih,
    const float* __restrict__ b_hh) {
    __shared__ int sids[GBM];
    __shared__ __align__(16) float As[2][GBK][GBM + 4];
    __shared__ __align__(16) float Bs[2][GBK][GBN + 4];

    int tid = threadIdx.x;
    int bm = blockIdx.y, bn = blockIdx.x;
    int tx = tid & 15, ty = tid >> 4;
    int lrow = tid >> 1;
    int lk   = (tid & 1) << 2;

    if (tid < GBM) sids[tid] = __ldg(&sentence[bm * GBM + tid]);
    __syncthreads();

    const float* aptr = emb + (size_t)sids[lrow] * EMB + lk;
    const float* bptr = W_ih + (size_t)(bn * GBN + lrow) * EMB + lk;

    {
        float4 av = *(const float4*)aptr;
        float4 bv = *(const float4*)bptr;
        As[0][lk + 0][lrow] = av.x; As[0][lk + 1][lrow] = av.y;
        As[0][lk + 2][lrow] = av.z; As[0][lk + 3][lrow] = av.w;
        Bs[0][lk + 0][lrow] = bv.x; Bs[0][lk + 1][lrow] = bv.y;
        Bs[0][lk + 2][lrow] = bv.z; Bs[0][lk + 3][lrow] = bv.w;
    }
    __syncthreads();

    float acc[8][8] = {};
    int cur = 0;
    for (int kt = GBK; kt <= EMB; kt += GBK) {
        bool more = (kt < EMB);
        float4 av, bv;
        if (more) {
            av = *(const float4*)(aptr + kt);
            bv = *(const float4*)(bptr + kt);
        }
        #pragma unroll
        for (int kk = 0; kk < GBK; kk++) {
            float4 a0 = *(const float4*)&As[cur][kk][ty << 3];
            float4 a1 = *(const float4*)&As[cur][kk][(ty << 3) + 4];
            float4 b0 = *(const float4*)&Bs[cur][kk][tx << 3];
            float4 b1 = *(const float4*)&Bs[cur][kk][(tx << 3) + 4];
            float am[8] = {a0.x, a0.y, a0.z, a0.w, a1.x, a1.y, a1.z, a1.w};
            float bb[8] = {b0.x, b0.y, b0.z, b0.w, b1.x, b1.y, b1.z, b1.w};
            #pragma unroll
            for (int i = 0; i < 8; i++)
                #pragma unroll
                for (int j = 0; j < 8; j++)
                    acc[i][j] = fmaf(am[i], bb[j], acc[i][j]);
        }
        if (more) {
            int nxt = cur ^ 1;
            As[nxt][lk + 0][lrow] = av.x; As[nxt][lk + 1][lrow] = av.y;
            As[nxt][lk + 2][lrow] = av.z; As[nxt][lk + 3][lrow] = av.w;
            Bs[nxt][lk + 0][lrow] = bv.x; Bs[nxt][lk + 1][lrow] = bv.y;
            Bs[nxt][lk + 2][lrow] = bv.z; Bs[nxt][lk + 3][lrow] = bv.w;
            __syncthreads();
            cur = nxt;
        }
    }

    int n0 = bn * GBN + (tx << 3);
    float4 bi0 = *(const float4*)&b_ih[n0];
    float4 bi1 = *(const float4*)&b_ih[n0 + 4];
    float4 bh0 = *(const float4*)&b_hh[n0];
    float4 bh1 = *(const float4*)&b_hh[n0 + 4];
    float4 bl0, bl1;
    bl0.x = bi0.x + bh0.x; bl0.y = bi0.y + bh0.y;
    bl0.z = bi0.z + bh0.z; bl0.w = bi0.w + bh0.w;
    bl1.x = bi1.x + bh1.x; bl1.y = bi1.y + bh1.y;
    bl1.z = bi1.z + bh1.z; bl1.w = bi1.w + bh1.w;
    #pragma unroll
    for (int i = 0; i < 8; i++) {
        int m = bm * GBM + (ty << 3) + i;
        float4 o0, o1;
        o0.x = acc[i][0] + bl0.x; o0.y = acc[i][1] + bl0.y;
        o0.z = acc[i][2] + bl0.z; o0.w = acc[i][3] + bl0.w;
        o1.x = acc[i][4] + bl1.x; o1.y = acc[i][5] + bl1.y;
        o1.z = acc[i][6] + bl1.z; o1.w = acc[i][7] + bl1.w;
        float* dst = &g_xgates[(size_t)m * G4H + n0];
        *(float4*)dst = o0;
        *(float4*)(dst + 4) = o1;
    }
}

// ---------------- persistent LSTM recurrence: 4B slots + EARLY-release hint ----------------
// 128 blocks x 1024 threads. Block b owns hidden units [8b, 8b+8).
// Publish: warp0 (j==0) lanes st.relaxed.f32 (h + q?3:-3) to g_slot[t&1][unit];
//          lane0 red.relaxed(g_cnt, 1) as a pacing HINT.
// Wait:    warp1 lane0 polls cnt >= 128*(t-1) - EARLY (early release: ~80/128 done);
//          barrier; tid<256 stage 4 slots each with range-verified retry (the retry
//          absorbs the <=EARLY stragglers; ranges carry the actual correctness).
// Progress: a block can only PUBLISH step t after staging all of t-1, so block
// spread stays <= 1 step and every poll target is eventually reached.
__global__ void __launch_bounds__(1024, 1) lstm_rec(const float* __restrict__ W_hh) {
    __shared__ __align__(16) float sh_h[HID];
    __shared__ float part_s[8][4][4][4];

    int tid  = threadIdx.x;
    int lane = tid & 31, warp = tid >> 5;
    int group = warp >> 2, chunk = warp & 3;
    int b = blockIdx.x;
    int unit = b * UPB + group;

    // Packed register weights: w2[j][k] covers h pairs (chunk*128 + lane + 32k)
    unsigned long long w2[4][4];
    #pragma unroll
    for (int j = 0; j < 4; j++) {
        const float* wr = W_hh + (size_t)(j * HID + unit) * HID + (chunk << 8) + (lane << 1);
        #pragma unroll
        for (int k = 0; k < 4; k++)
            w2[j][k] = *(const unsigned long long*)(wr + 64 * k);
    }

    float c_reg = 0.f;
    float xg_cur = 0.f;
    if (warp == 0)
        xg_cur = __ldg(&g_xgates[(size_t)0 * G4H + (lane & 3) * HID + b * UPB + (lane >> 2)]);

    __syncthreads();

    int tgt = -EARLY;  // = NBLK * (t-1) - EARLY
    for (int t = 1; t <= S_LEN; t++, tgt += NBLK) {
        // Hint poll: warp1 lane0, 2-deep pipelined relaxed loads, EARLY-released
        if (tid == 32) {
            for (;;) {
                int a = ld_rlx32(&g_cnt);
                if (a >= tgt) break;
                int c = ld_rlx32(&g_cnt);
                if (c >= tgt) break;
            }
        }
        __syncthreads();  // A: most publishes observed; stragglers handled below

        // Warp 0: prefetch next step's xg (DRAM latency hidden across the step)
        float xg_nxt = 0.f;
        if (warp == 0) {
            int tp = (t < S_LEN) ? t : 0;
            xg_nxt = __ldg(&g_xgates[(size_t)tp * G4H + (lane & 3) * HID + b * UPB + (lane >> 2)]);
        }

        // Stage: tid<256 read 4 slots (2 x u64) each; range-verify 4B halves; decode
        if (tid < 256) {
            const unsigned long long* sp =
                (const unsigned long long*)&g_slot[(t - 1) & 1][tid << 2];
            const float off = (((t - 1) >> 1) & 1) ? 3.f : -3.f;   // writer's phase offset
            const float sgn = (((t - 1) >> 1) & 1) ? 1.f : -1.f;   // valid iff v*sgn > 1.5
            float4 hv;
            for (;;) {
                unsigned long long s0 = ld_rlx64(sp + 0);
                unsigned long long s1 = ld_rlx64(sp + 1);
                float2 a = unpack2(s0), c = unpack2(s1);
                bool ok = (a.x * sgn > 1.5f) & (a.y * sgn > 1.5f)
                        & (c.x * sgn > 1.5f) & (c.y * sgn > 1.5f);
                if (ok) {
                    hv.x = a.x - off; hv.y = a.y - off;   // exact (Sterbenz)
                    hv.z = c.x - off; hv.w = c.y - off;
                    break;
                }
            }
            *(float4*)&sh_h[tid << 2] = hv;
        }
        __syncthreads();  // B: staged h visible block-wide

        // Dots: thread's 4 h pairs at pair index chunk*128 + lane + 32k (conflict-free LDS)
        const unsigned long long* hp = (const unsigned long long*)sh_h + (chunk << 7) + lane;
        unsigned long long h0 = hp[0], h1 = hp[32], h2 = hp[64], h3 = hp[96];

        unsigned long long a2_0 = 0ull, a2_1 = 0ull, a2_2 = 0ull, a2_3 = 0ull;
        fma2(a2_0, w2[0][0], h0); fma2(a2_1, w2[1][0], h0);
        fma2(a2_2, w2[2][0], h0); fma2(a2_3, w2[3][0], h0);
        fma2(a2_0, w2[0][1], h1); fma2(a2_1, w2[1][1], h1);
        fma2(a2_2, w2[2][1], h1); fma2(a2_3, w2[3][1], h1);
        fma2(a2_0, w2[0][2], h2); fma2(a2_1, w2[1][2], h2);
        fma2(a2_2, w2[2][2], h2); fma2(a2_3, w2[3][2], h2);
        fma2(a2_0, w2[0][3], h3); fma2(a2_1, w2[1][3], h3);
        fma2(a2_2, w2[2][3], h3); fma2(a2_3, w2[3][3], h3);

        float2 f0 = unpack2(a2_0), f1 = unpack2(a2_1), f2 = unpack2(a2_2), f3 = unpack2(a2_3);
        float s0 = f0.x + f0.y, s1 = f1.x + f1.y, s2 = f2.x + f2.y, s3 = f3.x + f3.y;

        #pragma unroll
        for (int o = 16; o >= 4; o >>= 1) {
            s0 += __shfl_xor_sync(0xffffffffu, s0, o);
            s1 += __shfl_xor_sync(0xffffffffu, s1, o);
            s2 += __shfl_xor_sync(0xffffffffu, s2, o);
            s3 += __shfl_xor_sync(0xffffffffu, s3, o);
        }
        if (lane < 4) {
            part_s[group][0][chunk][lane] = s0;
            part_s[group][1][chunk][lane] = s1;
            part_s[group][2][chunk][lane] = s2;
            part_s[group][3][chunk][lane] = s3;
        }
        __syncthreads();  // C

        // Warp 0 tail: lane r = gate row (unit u=r>>2, gate j=r&3)
        if (warp == 0) {
            int u = lane >> 2, j = lane & 3;
            const float4* pp = (const float4*)&part_s[u][j][0][0];
            float4 p0 = pp[0], p1 = pp[1], p2 = pp[2], p3 = pp[3];
            float s = ((p0.x + p0.y) + (p0.z + p0.w)) + ((p1.x + p1.y) + (p1.z + p1.w))
                    + ((p2.x + p2.y) + (p2.z + p2.w)) + ((p3.x + p3.y) + (p3.z + p3.w))
                    + xg_cur;
            float act = (j == 2) ? tanh_fast(s) : sigm(s);
            float fv = __shfl_down_sync(0xffffffffu, act, 1);
            float gv = __shfl_down_sync(0xffffffffu, act, 2);
            float ov = __shfl_down_sync(0xffffffffu, act, 3);
            if (j == 0) {
                c_reg = fmaf(fv, c_reg, act * gv);          // act = i
                float h = ov * tanh_fast(c_reg);
                g_hs[(size_t)t * HID + b * UPB + u] = h;    // history (head), off-path
                float woff = ((t >> 1) & 1) ? 3.f : -3.f;   // this step's phase offset
                st_rlx32f(&g_slot[t & 1][b * UPB + u], h + woff);
            }
            __syncwarp();
            if (lane == 0) red_add_relaxed(&g_cnt, 1);      // hint only (ranges carry truth)
            xg_cur = xg_nxt;
        }
    }
}

// ---------------- head: out[s] = sigmoid(hs(s+1) . v + bc) ----------------
__global__ void head_kernel(float* __restrict__ out) {
    int s = blockIdx.x;
    int tid = threadIdx.x;  // 128
    const float* hrow = g_hs + (size_t)(s + 1) * HID;
    float p = 0.f;
    #pragma unroll
    for (int k = 0; k < 8; k++)
        p = fmaf(hrow[tid + 128 * k], g_v[tid + 128 * k], p);
    #pragma unroll
    for (int o = 16; o; o >>= 1) p += __shfl_xor_sync(0xffffffffu, p, o);
    __shared__ float red[4];
    if ((tid & 31) == 0) red[tid >> 5] = p;
    __syncthreads();
    if (tid == 0) {
        float tot = red[0] + red[1] + red[2] + red[3] + g_bc;
        out[s] = sigm(tot);
    }
}

// ---------------- launch ----------------
extern "C" void kernel_launch(void* const* d_in, const int* in_sizes, int n_in,
                              void* d_out, int out_size) {
    const int*   sentence = (const int*)  d_in[0];
    const float* emb      = (const float*)d_in[1];
    const float* W_ih     = (const float*)d_in[2];
    const float* W_hh     = (const float*)d_in[3];
    const float* b_ih     = (const float*)d_in[4];
    const float* b_hh     = (const float*)d_in[5];
    const float* W_tag    = (const float*)d_in[6];
    const float* b_tag    = (const float*)d_in[7];
    const float* W_hyb    = (const float*)d_in[8];
    const float* b_hyb    = (const float*)d_in[9];
    float* out = (float*)d_out;

    init_kernel<<<1, 1024>>>(b_tag, W_hyb, b_hyb);
    vprec_kernel<<<1, 1024>>>(W_tag, W_hyb);
    dim3 g(G4H / GBN, S_LEN / GBM);
    gemm_xgates<<<g, 256>>>(sentence, emb, W_ih, b_ih, b_hh);
    lstm_rec<<<NBLK, 1024>>>(W_hh);
    head_kernel<<<S_LEN, 128>>>(out);
}

// round 15
// speedup vs baseline: 1.2867x; 1.0578x over previous
#include <cuda_runtime.h>
#include <cstdint>
#include <cstddef>

// Problem dims
#define S_LEN 4096
#define HID   1024
#define EMB   1024
#define G4H   4096   // 4*HID
#define NBLK  128    // persistent recurrence blocks (1 per SM)
#define UPB   8      // hidden units per block (128*8 = 1024)
#define EARLY 96     // hint-poll early-release margin (stagers' retry absorbs stragglers)

// ---------------- scratch (static device memory; no allocation) ----------------
__device__ __align__(16) float g_xgates[(size_t)S_LEN * G4H];   // 67 MB
__device__ __align__(16) float g_hs[(size_t)(S_LEN + 1) * HID]; // h history (head input)
// Sync slots: 4B range-encoded h. v = h + (q ? +3 : -3), q = (t>>1)&1, buffer = t&1.
// |h|<1 strictly => v in (2,4) or (-4,-2); phase is carried inside the payload.
__device__ __align__(16) float g_slot[2][HID];
__device__ int   g_cnt;                                          // completion hint counter
__device__ float g_v[HID];                                       // W_tag^T @ w_hyb
__device__ float g_bc;                                           // b_tag.w_hyb + b_hyb

// ---------------- helpers (morally-strong relaxed ops: coherent, per-address atomic) ----------------
__device__ __forceinline__ int ld_rlx32(const int* p) {
    int v;
    asm volatile("ld.global.relaxed.gpu.b32 %0, [%1];" : "=r"(v) : "l"(p) : "memory");
    return v;
}
__device__ __forceinline__ unsigned long long ld_rlx64(const unsigned long long* p) {
    unsigned long long v;
    asm volatile("ld.global.relaxed.gpu.b64 %0, [%1];" : "=l"(v) : "l"(p) : "memory");
    return v;
}
__device__ __forceinline__ void st_rlx32f(float* p, float v) {
    asm volatile("st.global.relaxed.gpu.f32 [%0], %1;" :: "l"(p), "f"(v) : "memory");
}
__device__ __forceinline__ void red_add_relaxed(int* p, int v) {
    asm volatile("red.relaxed.gpu.global.add.s32 [%0], %1;" :: "l"(p), "r"(v) : "memory");
}
__device__ __forceinline__ void fma2(unsigned long long& d, unsigned long long a, unsigned long long b) {
    asm("fma.rn.f32x2 %0, %1, %2, %0;" : "+l"(d) : "l"(a), "l"(b));
}
__device__ __forceinline__ float2 unpack2(unsigned long long v) {
    float2 f;
    asm("mov.b64 {%0,%1}, %2;" : "=f"(f.x), "=f"(f.y) : "l"(v));
    return f;
}
__device__ __forceinline__ float sigm(float x) { return 1.f / (1.f + __expf(-x)); }
__device__ __forceinline__ float tanh_fast(float x) { return 2.f / (1.f + __expf(-2.f * x)) - 1.f; }

// ---------------- init: slots reset (both buffers), counter = 0, head bias constant ----------------
__global__ void init_kernel(const float* __restrict__ b_tag,
                            const float* __restrict__ w_hyb,
                            const float* __restrict__ b_hyb) {
    int tid = threadIdx.x;               // 1024 threads
    if (tid < HID) {
        g_slot[0][tid] = -3.f;           // step 0: h=0, q=0 -> v = 0 - 3
        g_slot[1][tid] = 0.f;            // invalid (in neither valid range)
    }
    if (tid == 0) g_cnt = 0;
    if (tid < 32) {
        float s = 0.f;
        for (int k = tid; k < HID; k += 32) s = fmaf(b_tag[k], w_hyb[k], s);
        #pragma unroll
        for (int o = 16; o; o >>= 1) s += __shfl_xor_sync(0xffffffffu, s, o);
        if (tid == 0) g_bc = s + b_hyb[0];
    }
}

// ---------------- head precompute: v[j] = sum_t w_hyb[t] * W_tag[t][j] ----------------
__global__ void vprec_kernel(const float* __restrict__ W_tag,
                             const float* __restrict__ w_hyb) {
    int j = threadIdx.x;  // 1024 threads
    float s = 0.f;
    #pragma unroll 8
    for (int t = 0; t < HID; t++)
        s = fmaf(__ldg(&w_hyb[t]), __ldg(&W_tag[(size_t)t * HID + j]), s);
    g_v[j] = s;
}

// ---------------- front GEMM: g_xgates[s][n] = emb[sentence[s]] . W_ih[n] + bias ----------------
#define GBM 128
#define GBN 128
#define GBK 8

__global__ void __launch_bounds__(256) gemm_xgates(
    const int*   __restrict__ sentence,
    const float* __restrict__ emb,
    const float* __restrict__ W_ih,
    const float* __restrict__ b_ih,
    const float* __restrict__ b_hh) {
    __shared__ int sids[GBM];
    __shared__ __align__(16) float As[2][GBK][GBM + 4];
    __shared__ __align__(16) float Bs[2][GBK][GBN + 4];

    int tid = threadIdx.x;
    int bm = blockIdx.y, bn = blockIdx.x;
    int tx = tid & 15, ty = tid >> 4;
    int lrow = tid >> 1;
    int lk   = (tid & 1) << 2;

    if (tid < GBM) sids[tid] = __ldg(&sentence[bm * GBM + tid]);
    __syncthreads();

    const float* aptr = emb + (size_t)sids[lrow] * EMB + lk;
    const float* bptr = W_ih + (size_t)(bn * GBN + lrow) * EMB + lk;

    {
        float4 av = *(const float4*)aptr;
        float4 bv = *(const float4*)bptr;
        As[0][lk + 0][lrow] = av.x; As[0][lk + 1][lrow] = av.y;
        As[0][lk + 2][lrow] = av.z; As[0][lk + 3][lrow] = av.w;
        Bs[0][lk + 0][lrow] = bv.x; Bs[0][lk + 1][lrow] = bv.y;
        Bs[0][lk + 2][lrow] = bv.z; Bs[0][lk + 3][lrow] = bv.w;
    }
    __syncthreads();

    float acc[8][8] = {};
    int cur = 0;
    for (int kt = GBK; kt <= EMB; kt += GBK) {
        bool more = (kt < EMB);
        float4 av, bv;
        if (more) {
            av = *(const float4*)(aptr + kt);
            bv = *(const float4*)(bptr + kt);
        }
        #pragma unroll
        for (int kk = 0; kk < GBK; kk++) {
            float4 a0 = *(const float4*)&As[cur][kk][ty << 3];
            float4 a1 = *(const float4*)&As[cur][kk][(ty << 3) + 4];
            float4 b0 = *(const float4*)&Bs[cur][kk][tx << 3];
            float4 b1 = *(const float4*)&Bs[cur][kk][(tx << 3) + 4];
            float am[8] = {a0.x, a0.y, a0.z, a0.w, a1.x, a1.y, a1.z, a1.w};
            float bb[8] = {b0.x, b0.y, b0.z, b0.w, b1.x, b1.y, b1.z, b1.w};
            #pragma unroll
            for (int i = 0; i < 8; i++)
                #pragma unroll
                for (int j = 0; j < 8; j++)
                    acc[i][j] = fmaf(am[i], bb[j], acc[i][j]);
        }
        if (more) {
            int nxt = cur ^ 1;
            As[nxt][lk + 0][lrow] = av.x; As[nxt][lk + 1][lrow] = av.y;
            As[nxt][lk + 2][lrow] = av.z; As[nxt][lk + 3][lrow] = av.w;
            Bs[nxt][lk + 0][lrow] = bv.x; Bs[nxt][lk + 1][lrow] = bv.y;
            Bs[nxt][lk + 2][lrow] = bv.z; Bs[nxt][lk + 3][lrow] = bv.w;
            __syncthreads();
            cur = nxt;
        }
    }

    int n0 = bn * GBN + (tx << 3);
    float4 bi0 = *(const float4*)&b_ih[n0];
    float4 bi1 = *(const float4*)&b_ih[n0 + 4];
    float4 bh0 = *(const float4*)&b_hh[n0];
    float4 bh1 = *(const float4*)&b_hh[n0 + 4];
    float4 bl0, bl1;
    bl0.x = bi0.x + bh0.x; bl0.y = bi0.y + bh0.y;
    bl0.z = bi0.z + bh0.z; bl0.w = bi0.w + bh0.w;
    bl1.x = bi1.x + bh1.x; bl1.y = bi1.y + bh1.y;
    bl1.z = bi1.z + bh1.z; bl1.w = bi1.w + bh1.w;
    #pragma unroll
    for (int i = 0; i < 8; i++) {
        int m = bm * GBM + (ty << 3) + i;
        float4 o0, o1;
        o0.x = acc[i][0] + bl0.x; o0.y = acc[i][1] + bl0.y;
        o0.z = acc[i][2] + bl0.z; o0.w = acc[i][3] + bl0.w;
        o1.x = acc[i][4] + bl1.x; o1.y = acc[i][5] + bl1.y;
        o1.z = acc[i][6] + bl1.z; o1.w = acc[i][7] + bl1.w;
        float* dst = &g_xgates[(size_t)m * G4H + n0];
        *(float4*)dst = o0;
        *(float4*)(dst + 4) = o1;
    }
}

// ---------------- persistent LSTM recurrence: 4B slots + EARLY-release hint ----------------
// 128 blocks x 1024 threads. Block b owns hidden units [8b, 8b+8).
// Publish: warp0 (j==0) lanes st.relaxed.f32 (h + q?3:-3) to g_slot[t&1][unit];
//          lane0 red.relaxed(g_cnt, 1) as a pacing HINT.
// Wait:    warp1 lane0 polls cnt >= 128*(t-1) - EARLY (early release: ~32/128 done);
//          barrier; tid<256 stage 4 slots each with range-verified retry (the retry
//          absorbs the <=EARLY stragglers; ranges carry the actual correctness).
// Progress: a block can only PUBLISH step t after staging all of t-1, so block
// spread stays <= 1 step and every poll target is eventually reached.
__global__ void __launch_bounds__(1024, 1) lstm_rec(const float* __restrict__ W_hh) {
    __shared__ __align__(16) float sh_h[HID];
    __shared__ float part_s[8][4][4][4];

    int tid  = threadIdx.x;
    int lane = tid & 31, warp = tid >> 5;
    int group = warp >> 2, chunk = warp & 3;
    int b = blockIdx.x;
    int unit = b * UPB + group;

    // Packed register weights: w2[j][k] covers h pairs (chunk*128 + lane + 32k)
    unsigned long long w2[4][4];
    #pragma unroll
    for (int j = 0; j < 4; j++) {
        const float* wr = W_hh + (size_t)(j * HID + unit) * HID + (chunk << 8) + (lane << 1);
        #pragma unroll
        for (int k = 0; k < 4; k++)
            w2[j][k] = *(const unsigned long long*)(wr + 64 * k);
    }

    float c_reg = 0.f;
    float xg_cur = 0.f;
    if (warp == 0)
        xg_cur = __ldg(&g_xgates[(size_t)0 * G4H + (lane & 3) * HID + b * UPB + (lane >> 2)]);

    __syncthreads();

    int tgt = -EARLY;  // = NBLK * (t-1) - EARLY
    for (int t = 1; t <= S_LEN; t++, tgt += NBLK) {
        // Hint poll: warp1 lane0, 2-deep pipelined relaxed loads, EARLY-released
        if (tid == 32) {
            for (;;) {
                int a = ld_rlx32(&g_cnt);
                if (a >= tgt) break;
                int c = ld_rlx32(&g_cnt);
                if (c >= tgt) break;
            }
        }
        __syncthreads();  // A: most publishes observed; stragglers handled below

        // Warp 0: prefetch next step's xg (DRAM latency hidden across the step)
        float xg_nxt = 0.f;
        if (warp == 0) {
            int tp = (t < S_LEN) ? t : 0;
            xg_nxt = __ldg(&g_xgates[(size_t)tp * G4H + (lane & 3) * HID + b * UPB + (lane >> 2)]);
        }

        // Stage: tid<256 read 4 slots (2 x u64) each; range-verify 4B halves; decode
        if (tid < 256) {
            const unsigned long long* sp =
                (const unsigned long long*)&g_slot[(t - 1) & 1][tid << 2];
            const float off = (((t - 1) >> 1) & 1) ? 3.f : -3.f;   // writer's phase offset
            const float sgn = (((t - 1) >> 1) & 1) ? 1.f : -1.f;   // valid iff v*sgn > 1.5
            float4 hv;
            for (;;) {
                unsigned long long s0 = ld_rlx64(sp + 0);
                unsigned long long s1 = ld_rlx64(sp + 1);
                float2 a = unpack2(s0), c = unpack2(s1);
                bool ok = (a.x * sgn > 1.5f) & (a.y * sgn > 1.5f)
                        & (c.x * sgn > 1.5f) & (c.y * sgn > 1.5f);
                if (ok) {
                    hv.x = a.x - off; hv.y = a.y - off;   // exact (Sterbenz)
                    hv.z = c.x - off; hv.w = c.y - off;
                    break;
                }
            }
            *(float4*)&sh_h[tid << 2] = hv;
        }
        __syncthreads();  // B: staged h visible block-wide

        // Dots: thread's 4 h pairs at pair index chunk*128 + lane + 32k (conflict-free LDS)
        const unsigned long long* hp = (const unsigned long long*)sh_h + (chunk << 7) + lane;
        unsigned long long h0 = hp[0], h1 = hp[32], h2 = hp[64], h3 = hp[96];

        unsigned long long a2_0 = 0ull, a2_1 = 0ull, a2_2 = 0ull, a2_3 = 0ull;
        fma2(a2_0, w2[0][0], h0); fma2(a2_1, w2[1][0], h0);
        fma2(a2_2, w2[2][0], h0); fma2(a2_3, w2[3][0], h0);
        fma2(a2_0, w2[0][1], h1); fma2(a2_1, w2[1][1], h1);
        fma2(a2_2, w2[2][1], h1); fma2(a2_3, w2[3][1], h1);
        fma2(a2_0, w2[0][2], h2); fma2(a2_1, w2[1][2], h2);
        fma2(a2_2, w2[2][2], h2); fma2(a2_3, w2[3][2], h2);
        fma2(a2_0, w2[0][3], h3); fma2(a2_1, w2[1][3], h3);
        fma2(a2_2, w2[2][3], h3); fma2(a2_3, w2[3][3], h3);

        float2 f0 = unpack2(a2_0), f1 = unpack2(a2_1), f2 = unpack2(a2_2), f3 = unpack2(a2_3);
        float s0 = f0.x + f0.y, s1 = f1.x + f1.y, s2 = f2.x + f2.y, s3 = f3.x + f3.y;

        #pragma unroll
        for (int o = 16; o >= 4; o >>= 1) {
            s0 += __shfl_xor_sync(0xffffffffu, s0, o);
            s1 += __shfl_xor_sync(0xffffffffu, s1, o);
            s2 += __shfl_xor_sync(0xffffffffu, s2, o);
            s3 += __shfl_xor_sync(0xffffffffu, s3, o);
        }
        if (lane < 4) {
            part_s[group][0][chunk][lane] = s0;
            part_s[group][1][chunk][lane] = s1;
            part_s[group][2][chunk][lane] = s2;
            part_s[group][3][chunk][lane] = s3;
        }
        __syncthreads();  // C

        // Warp 0 tail: lane r = gate row (unit u=r>>2, gate j=r&3)
        if (warp == 0) {
            int u = lane >> 2, j = lane & 3;
            const float4* pp = (const float4*)&part_s[u][j][0][0];
            float4 p0 = pp[0], p1 = pp[1], p2 = pp[2], p3 = pp[3];
            float s = ((p0.x + p0.y) + (p0.z + p0.w)) + ((p1.x + p1.y) + (p1.z + p1.w))
                    + ((p2.x + p2.y) + (p2.z + p2.w)) + ((p3.x + p3.y) + (p3.z + p3.w))
                    + xg_cur;
            float act = (j == 2) ? tanh_fast(s) : sigm(s);
            float fv = __shfl_down_sync(0xffffffffu, act, 1);
            float gv = __shfl_down_sync(0xffffffffu, act, 2);
            float ov = __shfl_down_sync(0xffffffffu, act, 3);
            if (j == 0) {
                c_reg = fmaf(fv, c_reg, act * gv);          // act = i
                float h = ov * tanh_fast(c_reg);
                g_hs[(size_t)t * HID + b * UPB + u] = h;    // history (head), off-path
                float woff = ((t >> 1) & 1) ? 3.f : -3.f;   // this step's phase offset
                st_rlx32f(&g_slot[t & 1][b * UPB + u], h + woff);
            }
            __syncwarp();
            if (lane == 0) red_add_relaxed(&g_cnt, 1);      // hint only (ranges carry truth)
            xg_cur = xg_nxt;
        }
    }
}

// ---------------- head: out[s] = sigmoid(hs(s+1) . v + bc) ----------------
__global__ void head_kernel(float* __restrict__ out) {
    int s = blockIdx.x;
    int tid = threadIdx.x;  // 128
    const float* hrow = g_hs + (size_t)(s + 1) * HID;
    float p = 0.f;
    #pragma unroll
    for (int k = 0; k < 8; k++)
        p = fmaf(hrow[tid + 128 * k], g_v[tid + 128 * k], p);
    #pragma unroll
    for (int o = 16; o; o >>= 1) p += __shfl_xor_sync(0xffffffffu, p, o);
    __shared__ float red[4];
    if ((tid & 31) == 0) red[tid >> 5] = p;
    __syncthreads();
    if (tid == 0) {
        float tot = red[0] + red[1] + red[2] + red[3] + g_bc;
        out[s] = sigm(tot);
    }
}

// ---------------- launch ----------------
extern "C" void kernel_launch(void* const* d_in, const int* in_sizes, int n_in,
                              void* d_out, int out_size) {
    const int*   sentence = (const int*)  d_in[0];
    const float* emb      = (const float*)d_in[1];
    const float* W_ih     = (const float*)d_in[2];
    const float* W_hh     = (const float*)d_in[3];
    const float* b_ih     = (const float*)d_in[4];
    const float* b_hh     = (const float*)d_in[5];
    const float* W_tag    = (const float*)d_in[6];
    const float* b_tag    = (const float*)d_in[7];
    const float* W_hyb    = (const float*)d_in[8];
    const float* b_hyb    = (const float*)d_in[9];
    float* out = (float*)d_out;

    init_kernel<<<1, 1024>>>(b_tag, W_hyb, b_hyb);
    vprec_kernel<<<1, 1024>>>(W_tag, W_hyb);
    dim3 g(G4H / GBN, S_LEN / GBM);
    gemm_xgates<<<g, 256>>>(sentence, emb, W_ih, b_ih, b_hh);
    lstm_rec<<<NBLK, 1024>>>(W_hh);
    head_kernel<<<S_LEN, 128>>>(out);
}

// round 16
// speedup vs baseline: 1.3452x; 1.0454x over previous
#include <cuda_runtime.h>
#include <cstdint>
#include <cstddef>

// Problem dims
#define S_LEN 4096
#define HID   1024
#define EMB   1024
#define G4H   4096   // 4*HID
#define NBLK  128    // persistent recurrence blocks (1 per SM)
#define UPB   8      // hidden units per block (128*8 = 1024)
#define EARLY 120    // hint-poll early-release margin (release after ~8 publishes seen)

// ---------------- scratch (static device memory; no allocation) ----------------
__device__ __align__(16) float g_xgates[(size_t)S_LEN * G4H];   // 67 MB
__device__ __align__(16) float g_hs[(size_t)(S_LEN + 1) * HID]; // h history (head input)
// Sync slots: 4B range-encoded h. v = h + (q ? +3 : -3), q = (t>>1)&1, buffer = t&1.
// |h|<1 strictly => v in (2,4) or (-4,-2); phase is carried inside the payload.
__device__ __align__(16) float g_slot[2][HID];
__device__ int   g_cnt;                                          // completion hint counter
__device__ float g_v[HID];                                       // W_tag^T @ w_hyb
__device__ float g_bc;                                           // b_tag.w_hyb + b_hyb

// ---------------- helpers (morally-strong relaxed ops: coherent, per-address atomic) ----------------
__device__ __forceinline__ int ld_rlx32(const int* p) {
    int v;
    asm volatile("ld.global.relaxed.gpu.b32 %0, [%1];" : "=r"(v) : "l"(p) : "memory");
    return v;
}
__device__ __forceinline__ unsigned long long ld_rlx64(const unsigned long long* p) {
    unsigned long long v;
    asm volatile("ld.global.relaxed.gpu.b64 %0, [%1];" : "=l"(v) : "l"(p) : "memory");
    return v;
}
__device__ __forceinline__ void st_rlx32f(float* p, float v) {
    asm volatile("st.global.relaxed.gpu.f32 [%0], %1;" :: "l"(p), "f"(v) : "memory");
}
__device__ __forceinline__ void red_add_relaxed(int* p, int v) {
    asm volatile("red.relaxed.gpu.global.add.s32 [%0], %1;" :: "l"(p), "r"(v) : "memory");
}
__device__ __forceinline__ void fma2(unsigned long long& d, unsigned long long a, unsigned long long b) {
    asm("fma.rn.f32x2 %0, %1, %2, %0;" : "+l"(d) : "l"(a), "l"(b));
}
__device__ __forceinline__ float2 unpack2(unsigned long long v) {
    float2 f;
    asm("mov.b64 {%0,%1}, %2;" : "=f"(f.x), "=f"(f.y) : "l"(v));
    return f;
}
__device__ __forceinline__ float sigm(float x) { return 1.f / (1.f + __expf(-x)); }
__device__ __forceinline__ float tanh_fast(float x) { return 2.f / (1.f + __expf(-2.f * x)) - 1.f; }

// ---------------- init: slots reset (both buffers), counter = 0, head bias constant ----------------
__global__ void init_kernel(const float* __restrict__ b_tag,
                            const float* __restrict__ w_hyb,
                            const float* __restrict__ b_hyb) {
    int tid = threadIdx.x;               // 1024 threads
    if (tid < HID) {
        g_slot[0][tid] = -3.f;           // step 0: h=0, q=0 -> v = 0 - 3
        g_slot[1][tid] = 0.f;            // invalid (in neither valid range)
    }
    if (tid == 0) g_cnt = 0;
    if (tid < 32) {
        float s = 0.f;
        for (int k = tid; k < HID; k += 32) s = fmaf(b_tag[k], w_hyb[k], s);
        #pragma unroll
        for (int o = 16; o; o >>= 1) s += __shfl_xor_sync(0xffffffffu, s, o);
        if (tid == 0) g_bc = s + b_hyb[0];
    }
}

// ---------------- head precompute: v[j] = sum_t w_hyb[t] * W_tag[t][j] ----------------
__global__ void vprec_kernel(const float* __restrict__ W_tag,
                             const float* __restrict__ w_hyb) {
    int j = threadIdx.x;  // 1024 threads
    float s = 0.f;
    #pragma unroll 8
    for (int t = 0; t < HID; t++)
        s = fmaf(__ldg(&w_hyb[t]), __ldg(&W_tag[(size_t)t * HID + j]), s);
    g_v[j] = s;
}

// ---------------- front GEMM: g_xgates[s][n] = emb[sentence[s]] . W_ih[n] + bias ----------------
#define GBM 128
#define GBN 128
#define GBK 8

__global__ void __launch_bounds__(256) gemm_xgates(
    const int*   __restrict__ sentence,
    const float* __restrict__ emb,
    const float* __restrict__ W_ih,
    const float* __restrict__ b_ih,
    const float* __restrict__ b_hh) {
    __shared__ int sids[GBM];
    __shared__ __align__(16) float As[2][GBK][GBM + 4];
    __shared__ __align__(16) float Bs[2][GBK][GBN + 4];

    int tid = threadIdx.x;
    int bm = blockIdx.y, bn = blockIdx.x;
    int tx = tid & 15, ty = tid >> 4;
    int lrow = tid >> 1;
    int lk   = (tid & 1) << 2;

    if (tid < GBM) sids[tid] = __ldg(&sentence[bm * GBM + tid]);
    __syncthreads();

    const float* aptr = emb + (size_t)sids[lrow] * EMB + lk;
    const float* bptr = W_ih + (size_t)(bn * GBN + lrow) * EMB + lk;

    {
        float4 av = *(const float4*)aptr;
        float4 bv = *(const float4*)bptr;
        As[0][lk + 0][lrow] = av.x; As[0][lk + 1][lrow] = av.y;
        As[0][lk + 2][lrow] = av.z; As[0][lk + 3][lrow] = av.w;
        Bs[0][lk + 0][lrow] = bv.x; Bs[0][lk + 1][lrow] = bv.y;
        Bs[0][lk + 2][lrow] = bv.z; Bs[0][lk + 3][lrow] = bv.w;
    }
    __syncthreads();

    float acc[8][8] = {};
    int cur = 0;
    for (int kt = GBK; kt <= EMB; kt += GBK) {
        bool more = (kt < EMB);
        float4 av, bv;
        if (more) {
            av = *(const float4*)(aptr + kt);
            bv = *(const float4*)(bptr + kt);
        }
        #pragma unroll
        for (int kk = 0; kk < GBK; kk++) {
            float4 a0 = *(const float4*)&As[cur][kk][ty << 3];
            float4 a1 = *(const float4*)&As[cur][kk][(ty << 3) + 4];
            float4 b0 = *(const float4*)&Bs[cur][kk][tx << 3];
            float4 b1 = *(const float4*)&Bs[cur][kk][(tx << 3) + 4];
            float am[8] = {a0.x, a0.y, a0.z, a0.w, a1.x, a1.y, a1.z, a1.w};
            float bb[8] = {b0.x, b0.y, b0.z, b0.w, b1.x, b1.y, b1.z, b1.w};
            #pragma unroll
            for (int i = 0; i < 8; i++)
                #pragma unroll
                for (int j = 0; j < 8; j++)
                    acc[i][j] = fmaf(am[i], bb[j], acc[i][j]);
        }
        if (more) {
            int nxt = cur ^ 1;
            As[nxt][lk + 0][lrow] = av.x; As[nxt][lk + 1][lrow] = av.y;
            As[nxt][lk + 2][lrow] = av.z; As[nxt][lk + 3][lrow] = av.w;
            Bs[nxt][lk + 0][lrow] = bv.x; Bs[nxt][lk + 1][lrow] = bv.y;
            Bs[nxt][lk + 2][lrow] = bv.z; Bs[nxt][lk + 3][lrow] = bv.w;
            __syncthreads();
            cur = nxt;
        }
    }

    int n0 = bn * GBN + (tx << 3);
    float4 bi0 = *(const float4*)&b_ih[n0];
    float4 bi1 = *(const float4*)&b_ih[n0 + 4];
    float4 bh0 = *(const float4*)&b_hh[n0];
    float4 bh1 = *(const float4*)&b_hh[n0 + 4];
    float4 bl0, bl1;
    bl0.x = bi0.x + bh0.x; bl0.y = bi0.y + bh0.y;
    bl0.z = bi0.z + bh0.z; bl0.w = bi0.w + bh0.w;
    bl1.x = bi1.x + bh1.x; bl1.y = bi1.y + bh1.y;
    bl1.z = bi1.z + bh1.z; bl1.w = bi1.w + bh1.w;
    #pragma unroll
    for (int i = 0; i < 8; i++) {
        int m = bm * GBM + (ty << 3) + i;
        float4 o0, o1;
        o0.x = acc[i][0] + bl0.x; o0.y = acc[i][1] + bl0.y;
        o0.z = acc[i][2] + bl0.z; o0.w = acc[i][3] + bl0.w;
        o1.x = acc[i][4] + bl1.x; o1.y = acc[i][5] + bl1.y;
        o1.z = acc[i][6] + bl1.z; o1.w = acc[i][7] + bl1.w;
        float* dst = &g_xgates[(size_t)m * G4H + n0];
        *(float4*)dst = o0;
        *(float4*)(dst + 4) = o1;
    }
}

// ---------------- persistent LSTM recurrence: 4B slots + EARLY-release hint ----------------
// 128 blocks x 1024 threads. Block b owns hidden units [8b, 8b+8).
// Publish: warp0 (j==0) lanes st.relaxed.f32 (h + q?3:-3) to g_slot[t&1][unit];
//          lane0 red.relaxed(g_cnt, 1) as a pacing HINT.
// Wait:    warp1 lane0 polls cnt >= 128*(t-1) - EARLY (release after ~8 publishes);
//          barrier; tid<256 stage 4 slots each with range-verified retry (the retry
//          absorbs the <=EARLY stragglers; ranges carry the actual correctness).
// Progress: a block can only PUBLISH step t after staging all of t-1, so block
// spread stays <= 1 step and every poll target is eventually reached.
__global__ void __launch_bounds__(1024, 1) lstm_rec(const float* __restrict__ W_hh) {
    __shared__ __align__(16) float sh_h[HID];
    __shared__ float part_s[8][4][4][4];

    int tid  = threadIdx.x;
    int lane = tid & 31, warp = tid >> 5;
    int group = warp >> 2, chunk = warp & 3;
    int b = blockIdx.x;
    int unit = b * UPB + group;

    // Packed register weights: w2[j][k] covers h pairs (chunk*128 + lane + 32k)
    unsigned long long w2[4][4];
    #pragma unroll
    for (int j = 0; j < 4; j++) {
        const float* wr = W_hh + (size_t)(j * HID + unit) * HID + (chunk << 8) + (lane << 1);
        #pragma unroll
        for (int k = 0; k < 4; k++)
            w2[j][k] = *(const unsigned long long*)(wr + 64 * k);
    }

    float c_reg = 0.f;
    float xg_cur = 0.f;
    if (warp == 0)
        xg_cur = __ldg(&g_xgates[(size_t)0 * G4H + (lane & 3) * HID + b * UPB + (lane >> 2)]);

    __syncthreads();

    int tgt = -EARLY;  // = NBLK * (t-1) - EARLY
    for (int t = 1; t <= S_LEN; t++, tgt += NBLK) {
        // Hint poll: warp1 lane0, 2-deep pipelined relaxed loads, EARLY-released
        if (tid == 32) {
            for (;;) {
                int a = ld_rlx32(&g_cnt);
                if (a >= tgt) break;
                int c = ld_rlx32(&g_cnt);
                if (c >= tgt) break;
            }
        }
        __syncthreads();  // A: pacing observed; stragglers handled below

        // Warp 0: prefetch next step's xg (DRAM latency hidden across the step)
        float xg_nxt = 0.f;
        if (warp == 0) {
            int tp = (t < S_LEN) ? t : 0;
            xg_nxt = __ldg(&g_xgates[(size_t)tp * G4H + (lane & 3) * HID + b * UPB + (lane >> 2)]);
        }

        // Stage: tid<256 read 4 slots (2 x u64) each; range-verify 4B halves; decode
        if (tid < 256) {
            const unsigned long long* sp =
                (const unsigned long long*)&g_slot[(t - 1) & 1][tid << 2];
            const float off = (((t - 1) >> 1) & 1) ? 3.f : -3.f;   // writer's phase offset
            const float sgn = (((t - 1) >> 1) & 1) ? 1.f : -1.f;   // valid iff v*sgn > 1.5
            float4 hv;
            for (;;) {
                unsigned long long s0 = ld_rlx64(sp + 0);
                unsigned long long s1 = ld_rlx64(sp + 1);
                float2 a = unpack2(s0), c = unpack2(s1);
                bool ok = (a.x * sgn > 1.5f) & (a.y * sgn > 1.5f)
                        & (c.x * sgn > 1.5f) & (c.y * sgn > 1.5f);
                if (ok) {
                    hv.x = a.x - off; hv.y = a.y - off;   // exact (Sterbenz)
                    hv.z = c.x - off; hv.w = c.y - off;
                    break;
                }
            }
            *(float4*)&sh_h[tid << 2] = hv;
        }
        __syncthreads();  // B: staged h visible block-wide

        // Dots: thread's 4 h pairs at pair index chunk*128 + lane + 32k (conflict-free LDS)
        const unsigned long long* hp = (const unsigned long long*)sh_h + (chunk << 7) + lane;
        unsigned long long h0 = hp[0], h1 = hp[32], h2 = hp[64], h3 = hp[96];

        unsigned long long a2_0 = 0ull, a2_1 = 0ull, a2_2 = 0ull, a2_3 = 0ull;
        fma2(a2_0, w2[0][0], h0); fma2(a2_1, w2[1][0], h0);
        fma2(a2_2, w2[2][0], h0); fma2(a2_3, w2[3][0], h0);
        fma2(a2_0, w2[0][1], h1); fma2(a2_1, w2[1][1], h1);
        fma2(a2_2, w2[2][1], h1); fma2(a2_3, w2[3][1], h1);
        fma2(a2_0, w2[0][2], h2); fma2(a2_1, w2[1][2], h2);
        fma2(a2_2, w2[2][2], h2); fma2(a2_3, w2[3][2], h2);
        fma2(a2_0, w2[0][3], h3); fma2(a2_1, w2[1][3], h3);
        fma2(a2_2, w2[2][3], h3); fma2(a2_3, w2[3][3], h3);

        float2 f0 = unpack2(a2_0), f1 = unpack2(a2_1), f2 = unpack2(a2_2), f3 = unpack2(a2_3);
        float s0 = f0.x + f0.y, s1 = f1.x + f1.y, s2 = f2.x + f2.y, s3 = f3.x + f3.y;

        #pragma unroll
        for (int o = 16; o >= 4; o >>= 1) {
            s0 += __shfl_xor_sync(0xffffffffu, s0, o);
            s1 += __shfl_xor_sync(0xffffffffu, s1, o);
            s2 += __shfl_xor_sync(0xffffffffu, s2, o);
            s3 += __shfl_xor_sync(0xffffffffu, s3, o);
        }
        if (lane < 4) {
            part_s[group][0][chunk][lane] = s0;
            part_s[group][1][chunk][lane] = s1;
            part_s[group][2][chunk][lane] = s2;
            part_s[group][3][chunk][lane] = s3;
        }
        __syncthreads();  // C

        // Warp 0 tail: lane r = gate row (unit u=r>>2, gate j=r&3)
        if (warp == 0) {
            int u = lane >> 2, j = lane & 3;
            const float4* pp = (const float4*)&part_s[u][j][0][0];
            float4 p0 = pp[0], p1 = pp[1], p2 = pp[2], p3 = pp[3];
            float s = ((p0.x + p0.y) + (p0.z + p0.w)) + ((p1.x + p1.y) + (p1.z + p1.w))
                    + ((p2.x + p2.y) + (p2.z + p2.w)) + ((p3.x + p3.y) + (p3.z + p3.w))
                    + xg_cur;
            float act = (j == 2) ? tanh_fast(s) : sigm(s);
            float fv = __shfl_down_sync(0xffffffffu, act, 1);
            float gv = __shfl_down_sync(0xffffffffu, act, 2);
            float ov = __shfl_down_sync(0xffffffffu, act, 3);
            if (j == 0) {
                c_reg = fmaf(fv, c_reg, act * gv);          // act = i
                float h = ov * tanh_fast(c_reg);
                g_hs[(size_t)t * HID + b * UPB + u] = h;    // history (head), off-path
                float woff = ((t >> 1) & 1) ? 3.f : -3.f;   // this step's phase offset
                st_rlx32f(&g_slot[t & 1][b * UPB + u], h + woff);
            }
            __syncwarp();
            if (lane == 0) red_add_relaxed(&g_cnt, 1);      // hint only (ranges carry truth)
            xg_cur = xg_nxt;
        }
    }
}

// ---------------- head: out[s] = sigmoid(hs(s+1) . v + bc) ----------------
__global__ void head_kernel(float* __restrict__ out) {
    int s = blockIdx.x;
    int tid = threadIdx.x;  // 128
    const float* hrow = g_hs + (size_t)(s + 1) * HID;
    float p = 0.f;
    #pragma unroll
    for (int k = 0; k < 8; k++)
        p = fmaf(hrow[tid + 128 * k], g_v[tid + 128 * k], p);
    #pragma unroll
    for (int o = 16; o; o >>= 1) p += __shfl_xor_sync(0xffffffffu, p, o);
    __shared__ float red[4];
    if ((tid & 31) == 0) red[tid >> 5] = p;
    __syncthreads();
    if (tid == 0) {
        float tot = red[0] + red[1] + red[2] + red[3] + g_bc;
        out[s] = sigm(tot);
    }
}

// ---------------- launch ----------------
extern "C" void kernel_launch(void* const* d_in, const int* in_sizes, int n_in,
                              void* d_out, int out_size) {
    const int*   sentence = (const int*)  d_in[0];
    const float* emb      = (const float*)d_in[1];
    const float* W_ih     = (const float*)d_in[2];
    const float* W_hh     = (const float*)d_in[3];
    const float* b_ih     = (const float*)d_in[4];
    const float* b_hh     = (const float*)d_in[5];
    const float* W_tag    = (const float*)d_in[6];
    const float* b_tag    = (const float*)d_in[7];
    const float* W_hyb    = (const float*)d_in[8];
    const float* b_hyb    = (const float*)d_in[9];
    float* out = (float*)d_out;

    init_kernel<<<1, 1024>>>(b_tag, W_hyb, b_hyb);
    vprec_kernel<<<1, 1024>>>(W_tag, W_hyb);
    dim3 g(G4H / GBN, S_LEN / GBM);
    gemm_xgates<<<g, 256>>>(sentence, emb, W_ih, b_ih, b_hh);
    lstm_rec<<<NBLK, 1024>>>(W_hh);
    head_kernel<<<S_LEN, 128>>>(out);
}

// round 17
// speedup vs baseline: 1.3704x; 1.0188x over previous
#include <cuda_runtime.h>
#include <cstdint>
#include <cstddef>

// Problem dims
#define S_LEN 4096
#define HID   1024
#define EMB   1024
#define G4H   4096   // 4*HID
#define NBLK  128    // persistent recurrence blocks (1 per SM)
#define UPB   8      // hidden units per block (128*8 = 1024)

// ---------------- scratch (static device memory; no allocation) ----------------
__device__ __align__(16) float g_xgates[(size_t)S_LEN * G4H];   // 67 MB
__device__ __align__(16) float g_hs[(size_t)(S_LEN + 1) * HID]; // h history (head input)
// Sync slots: 4B range-encoded h. v = h + (q ? +3 : -3), q = (t>>1)&1, buffer = t&1.
// |h|<1 strictly => v in (2,4) or (-4,-2); phase is carried inside the payload.
__device__ __align__(16) float g_slot[2][HID];
__device__ float g_v[HID];                                       // W_tag^T @ w_hyb
__device__ float g_bc;                                           // b_tag.w_hyb + b_hyb

// ---------------- helpers (morally-strong relaxed ops: coherent, per-address atomic) ----------------
__device__ __forceinline__ unsigned long long ld_rlx64(const unsigned long long* p) {
    unsigned long long v;
    asm volatile("ld.global.relaxed.gpu.b64 %0, [%1];" : "=l"(v) : "l"(p) : "memory");
    return v;
}
__device__ __forceinline__ void st_rlx32f(float* p, float v) {
    asm volatile("st.global.relaxed.gpu.f32 [%0], %1;" :: "l"(p), "f"(v) : "memory");
}
__device__ __forceinline__ void fma2(unsigned long long& d, unsigned long long a, unsigned long long b) {
    asm("fma.rn.f32x2 %0, %1, %2, %0;" : "+l"(d) : "l"(a), "l"(b));
}
__device__ __forceinline__ float2 unpack2(unsigned long long v) {
    float2 f;
    asm("mov.b64 {%0,%1}, %2;" : "=f"(f.x), "=f"(f.y) : "l"(v));
    return f;
}
__device__ __forceinline__ float sigm(float x) { return 1.f / (1.f + __expf(-x)); }
__device__ __forceinline__ float tanh_fast(float x) { return 2.f / (1.f + __expf(-2.f * x)) - 1.f; }

// ---------------- init: slots reset (both buffers), head bias constant ----------------
__global__ void init_kernel(const float* __restrict__ b_tag,
                            const float* __restrict__ w_hyb,
                            const float* __restrict__ b_hyb) {
    int tid = threadIdx.x;               // 1024 threads
    if (tid < HID) {
        g_slot[0][tid] = -3.f;           // step 0: h=0, q=0 -> v = 0 - 3
        g_slot[1][tid] = 0.f;            // invalid (in neither valid range)
    }
    if (tid < 32) {
        float s = 0.f;
        for (int k = tid; k < HID; k += 32) s = fmaf(b_tag[k], w_hyb[k], s);
        #pragma unroll
        for (int o = 16; o; o >>= 1) s += __shfl_xor_sync(0xffffffffu, s, o);
        if (tid == 0) g_bc = s + b_hyb[0];
    }
}

// ---------------- head precompute: v[j] = sum_t w_hyb[t] * W_tag[t][j] ----------------
__global__ void vprec_kernel(const float* __restrict__ W_tag,
                             const float* __restrict__ w_hyb) {
    int j = threadIdx.x;  // 1024 threads
    float s = 0.f;
    #pragma unroll 8
    for (int t = 0; t < HID; t++)
        s = fmaf(__ldg(&w_hyb[t]), __ldg(&W_tag[(size_t)t * HID + j]), s);
    g_v[j] = s;
}

// ---------------- front GEMM: g_xgates[s][n] = emb[sentence[s]] . W_ih[n] + bias ----------------
#define GBM 128
#define GBN 128
#define GBK 8

__global__ void __launch_bounds__(256) gemm_xgates(
    const int*   __restrict__ sentence,
    const float* __restrict__ emb,
    const float* __restrict__ W_ih,
    const float* __restrict__ b_ih,
    const float* __restrict__ b_hh) {
    __shared__ int sids[GBM];
    __shared__ __align__(16) float As[2][GBK][GBM + 4];
    __shared__ __align__(16) float Bs[2][GBK][GBN + 4];

    int tid = threadIdx.x;
    int bm = blockIdx.y, bn = blockIdx.x;
    int tx = tid & 15, ty = tid >> 4;
    int lrow = tid >> 1;
    int lk   = (tid & 1) << 2;

    if (tid < GBM) sids[tid] = __ldg(&sentence[bm * GBM + tid]);
    __syncthreads();

    const float* aptr = emb + (size_t)sids[lrow] * EMB + lk;
    const float* bptr = W_ih + (size_t)(bn * GBN + lrow) * EMB + lk;

    {
        float4 av = *(const float4*)aptr;
        float4 bv = *(const float4*)bptr;
        As[0][lk + 0][lrow] = av.x; As[0][lk + 1][lrow] = av.y;
        As[0][lk + 2][lrow] = av.z; As[0][lk + 3][lrow] = av.w;
        Bs[0][lk + 0][lrow] = bv.x; Bs[0][lk + 1][lrow] = bv.y;
        Bs[0][lk + 2][lrow] = bv.z; Bs[0][lk + 3][lrow] = bv.w;
    }
    __syncthreads();

    float acc[8][8] = {};
    int cur = 0;
    for (int kt = GBK; kt <= EMB; kt += GBK) {
        bool more = (kt < EMB);
        float4 av, bv;
        if (more) {
            av = *(const float4*)(aptr + kt);
            bv = *(const float4*)(bptr + kt);
        }
        #pragma unroll
        for (int kk = 0; kk < GBK; kk++) {
            float4 a0 = *(const float4*)&As[cur][kk][ty << 3];
            float4 a1 = *(const float4*)&As[cur][kk][(ty << 3) + 4];
            float4 b0 = *(const float4*)&Bs[cur][kk][tx << 3];
            float4 b1 = *(const float4*)&Bs[cur][kk][(tx << 3) + 4];
            float am[8] = {a0.x, a0.y, a0.z, a0.w, a1.x, a1.y, a1.z, a1.w};
            float bb[8] = {b0.x, b0.y, b0.z, b0.w, b1.x, b1.y, b1.z, b1.w};
            #pragma unroll
            for (int i = 0; i < 8; i++)
                #pragma unroll
                for (int j = 0; j < 8; j++)
                    acc[i][j] = fmaf(am[i], bb[j], acc[i][j]);
        }
        if (more) {
            int nxt = cur ^ 1;
            As[nxt][lk + 0][lrow] = av.x; As[nxt][lk + 1][lrow] = av.y;
            As[nxt][lk + 2][lrow] = av.z; As[nxt][lk + 3][lrow] = av.w;
            Bs[nxt][lk + 0][lrow] = bv.x; Bs[nxt][lk + 1][lrow] = bv.y;
            Bs[nxt][lk + 2][lrow] = bv.z; Bs[nxt][lk + 3][lrow] = bv.w;
            __syncthreads();
            cur = nxt;
        }
    }

    int n0 = bn * GBN + (tx << 3);
    float4 bi0 = *(const float4*)&b_ih[n0];
    float4 bi1 = *(const float4*)&b_ih[n0 + 4];
    float4 bh0 = *(const float4*)&b_hh[n0];
    float4 bh1 = *(const float4*)&b_hh[n0 + 4];
    float4 bl0, bl1;
    bl0.x = bi0.x + bh0.x; bl0.y = bi0.y + bh0.y;
    bl0.z = bi0.z + bh0.z; bl0.w = bi0.w + bh0.w;
    bl1.x = bi1.x + bh1.x; bl1.y = bi1.y + bh1.y;
    bl1.z = bi1.z + bh1.z; bl1.w = bi1.w + bh1.w;
    #pragma unroll
    for (int i = 0; i < 8; i++) {
        int m = bm * GBM + (ty << 3) + i;
        float4 o0, o1;
        o0.x = acc[i][0] + bl0.x; o0.y = acc[i][1] + bl0.y;
        o0.z = acc[i][2] + bl0.z; o0.w = acc[i][3] + bl0.w;
        o1.x = acc[i][4] + bl1.x; o1.y = acc[i][5] + bl1.y;
        o1.z = acc[i][6] + bl1.z; o1.w = acc[i][7] + bl1.w;
        float* dst = &g_xgates[(size_t)m * G4H + n0];
        *(float4*)dst = o0;
        *(float4*)(dst + 4) = o1;
    }
}

// ---------------- persistent LSTM recurrence: pure tag-spin (no counter, no hint) ----------------
// 128 blocks x 1024 threads. Block b owns hidden units [8b, 8b+8).
// Publish: warp0 (j==0) lanes st.relaxed.f32 (h + q?3:-3) to g_slot[t&1][unit].
//          The phase offset IS the flag; data and signal are the same 4B word.
// Wait:    tid<256 spin directly on their 4 slots (range checks). xg prefetch issues
//          first and hides under the spin. No counter, no poller warp, no barrier A.
// Safety:  double buffering by parity; worst-case stale value is step t-3 with the
//          OPPOSITE phase -> always distinguishable. Pure data dependency -> no deadlock.
__global__ void __launch_bounds__(1024, 1) lstm_rec(const float* __restrict__ W_hh) {
    __shared__ __align__(16) float sh_h[HID];
    __shared__ float part_s[8][4][4][4];

    int tid  = threadIdx.x;
    int lane = tid & 31, warp = tid >> 5;
    int group = warp >> 2, chunk = warp & 3;
    int b = blockIdx.x;
    int unit = b * UPB + group;

    // Packed register weights: w2[j][k] covers h pairs (chunk*128 + lane + 32k)
    unsigned long long w2[4][4];
    #pragma unroll
    for (int j = 0; j < 4; j++) {
        const float* wr = W_hh + (size_t)(j * HID + unit) * HID + (chunk << 8) + (lane << 1);
        #pragma unroll
        for (int k = 0; k < 4; k++)
            w2[j][k] = *(const unsigned long long*)(wr + 64 * k);
    }

    float c_reg = 0.f;
    float xg_cur = 0.f;
    if (warp == 0)
        xg_cur = __ldg(&g_xgates[(size_t)0 * G4H + (lane & 3) * HID + b * UPB + (lane >> 2)]);

    __syncthreads();

    for (int t = 1; t <= S_LEN; t++) {
        // Warp 0: prefetch next step's xg (DRAM latency hidden under the spin)
        float xg_nxt = 0.f;
        if (warp == 0) {
            int tp = (t < S_LEN) ? t : 0;
            xg_nxt = __ldg(&g_xgates[(size_t)tp * G4H + (lane & 3) * HID + b * UPB + (lane >> 2)]);
        }

        // Stage: tid<256 spin on 4 slots (2 x u64) each; range-verify 4B halves; decode
        if (tid < 256) {
            const unsigned long long* sp =
                (const unsigned long long*)&g_slot[(t - 1) & 1][tid << 2];
            const float off = (((t - 1) >> 1) & 1) ? 3.f : -3.f;   // writer's phase offset
            const float sgn = (((t - 1) >> 1) & 1) ? 1.f : -1.f;   // valid iff v*sgn > 1.5
            float4 hv;
            for (;;) {
                unsigned long long s0 = ld_rlx64(sp + 0);
                unsigned long long s1 = ld_rlx64(sp + 1);
                float2 a = unpack2(s0), c = unpack2(s1);
                bool ok = (a.x * sgn > 1.5f) & (a.y * sgn > 1.5f)
                        & (c.x * sgn > 1.5f) & (c.y * sgn > 1.5f);
                if (ok) {
                    hv.x = a.x - off; hv.y = a.y - off;   // exact (Sterbenz)
                    hv.z = c.x - off; hv.w = c.y - off;
                    break;
                }
            }
            *(float4*)&sh_h[tid << 2] = hv;
        }
        __syncthreads();  // B: staged h visible block-wide

        // Dots: thread's 4 h pairs at pair index chunk*128 + lane + 32k (conflict-free LDS)
        const unsigned long long* hp = (const unsigned long long*)sh_h + (chunk << 7) + lane;
        unsigned long long h0 = hp[0], h1 = hp[32], h2 = hp[64], h3 = hp[96];

        unsigned long long a2_0 = 0ull, a2_1 = 0ull, a2_2 = 0ull, a2_3 = 0ull;
        fma2(a2_0, w2[0][0], h0); fma2(a2_1, w2[1][0], h0);
        fma2(a2_2, w2[2][0], h0); fma2(a2_3, w2[3][0], h0);
        fma2(a2_0, w2[0][1], h1); fma2(a2_1, w2[1][1], h1);
        fma2(a2_2, w2[2][1], h1); fma2(a2_3, w2[3][1], h1);
        fma2(a2_0, w2[0][2], h2); fma2(a2_1, w2[1][2], h2);
        fma2(a2_2, w2[2][2], h2); fma2(a2_3, w2[3][2], h2);
        fma2(a2_0, w2[0][3], h3); fma2(a2_1, w2[1][3], h3);
        fma2(a2_2, w2[2][3], h3); fma2(a2_3, w2[3][3], h3);

        float2 f0 = unpack2(a2_0), f1 = unpack2(a2_1), f2 = unpack2(a2_2), f3 = unpack2(a2_3);
        float s0 = f0.x + f0.y, s1 = f1.x + f1.y, s2 = f2.x + f2.y, s3 = f3.x + f3.y;

        #pragma unroll
        for (int o = 16; o >= 4; o >>= 1) {
            s0 += __shfl_xor_sync(0xffffffffu, s0, o);
            s1 += __shfl_xor_sync(0xffffffffu, s1, o);
            s2 += __shfl_xor_sync(0xffffffffu, s2, o);
            s3 += __shfl_xor_sync(0xffffffffu, s3, o);
        }
        if (lane < 4) {
            part_s[group][0][chunk][lane] = s0;
            part_s[group][1][chunk][lane] = s1;
            part_s[group][2][chunk][lane] = s2;
            part_s[group][3][chunk][lane] = s3;
        }
        __syncthreads();  // C

        // Warp 0 tail: lane r = gate row (unit u=r>>2, gate j=r&3)
        if (warp == 0) {
            int u = lane >> 2, j = lane & 3;
            const float4* pp = (const float4*)&part_s[u][j][0][0];
            float4 p0 = pp[0], p1 = pp[1], p2 = pp[2], p3 = pp[3];
            float s = ((p0.x + p0.y) + (p0.z + p0.w)) + ((p1.x + p1.y) + (p1.z + p1.w))
                    + ((p2.x + p2.y) + (p2.z + p2.w)) + ((p3.x + p3.y) + (p3.z + p3.w))
                    + xg_cur;
            float act = (j == 2) ? tanh_fast(s) : sigm(s);
            float fv = __shfl_down_sync(0xffffffffu, act, 1);
            float gv = __shfl_down_sync(0xffffffffu, act, 2);
            float ov = __shfl_down_sync(0xffffffffu, act, 3);
            if (j == 0) {
                c_reg = fmaf(fv, c_reg, act * gv);          // act = i
                float h = ov * tanh_fast(c_reg);
                float woff = ((t >> 1) & 1) ? 3.f : -3.f;   // this step's phase offset
                st_rlx32f(&g_slot[t & 1][b * UPB + u], h + woff);  // data IS the flag
                g_hs[(size_t)t * HID + b * UPB + u] = h;    // history (head), off-path
            }
            xg_cur = xg_nxt;
        }
    }
}

// ---------------- head: out[s] = sigmoid(hs(s+1) . v + bc) ----------------
__global__ void head_kernel(float* __restrict__ out) {
    int s = blockIdx.x;
    int tid = threadIdx.x;  // 128
    const float* hrow = g_hs + (size_t)(s + 1) * HID;
    float p = 0.f;
    #pragma unroll
    for (int k = 0; k < 8; k++)
        p = fmaf(hrow[tid + 128 * k], g_v[tid + 128 * k], p);
    #pragma unroll
    for (int o = 16; o; o >>= 1) p += __shfl_xor_sync(0xffffffffu, p, o);
    __shared__ float red[4];
    if ((tid & 31) == 0) red[tid >> 5] = p;
    __syncthreads();
    if (tid == 0) {
        float tot = red[0] + red[1] + red[2] + red[3] + g_bc;
        out[s] = sigm(tot);
    }
}

// ---------------- launch ----------------
extern "C" void kernel_launch(void* const* d_in, const int* in_sizes, int n_in,
                              void* d_out, int out_size) {
    const int*   sentence = (const int*)  d_in[0];
    const float* emb      = (const float*)d_in[1];
    const float* W_ih     = (const float*)d_in[2];
    const float* W_hh     = (const float*)d_in[3];
    const float* b_ih     = (const float*)d_in[4];
    const float* b_hh     = (const float*)d_in[5];
    const float* W_tag    = (const float*)d_in[6];
    const float* b_tag    = (const float*)d_in[7];
    const float* W_hyb    = (const float*)d_in[8];
    const float* b_hyb    = (const float*)d_in[9];
    float* out = (float*)d_out;

    init_kernel<<<1, 1024>>>(b_tag, W_hyb, b_hyb);
    vprec_kernel<<<1, 1024>>>(W_tag, W_hyb);
    dim3 g(G4H / GBN, S_LEN / GBM);
    gemm_xgates<<<g, 256>>>(sentence, emb, W_ih, b_ih, b_hh);
    lstm_rec<<<NBLK, 1024>>>(W_hh);
    head_kernel<<<S_LEN, 128>>>(out);
}